// round 7
// baseline (speedup 1.0000x reference)
#include <cuda_runtime.h>
#include <math.h>
#include <cstdint>

// Shapes (fixed by the problem)
#define B_    2
#define I_    8
#define J_    1025
#define M_    256
#define H_    8
#define DH_   32
#define NSLAB 16              // B_*I_
#define RTOT  (NSLAB * J_)    // 16400
#define FF_   1024            // 4*M

typedef unsigned long long u64;

// ---- scratch (static __device__ arrays; no runtime allocation) ----
__device__ float g_sln[RTOT * M_];
__device__ float g_s2 [RTOT * M_];
__device__ float g_G  [NSLAB * M_ * M_];
__device__ float g_T  [NSLAB * M_ * M_];
__device__ float g_ET [NSLAB * M_ * M_];
__device__ float g_wosum[M_];
__device__ uint2 g_hln2[RTOT * M_];            // ln2 output, split hi/lo
__device__ uint2 g_h1hl[(size_t)RTOT * FF_];   // gelu(fc1) output, split hi/lo
__device__ uint2 g_w1hl[FF_ * M_];             // fc1_w split
__device__ uint2 g_w2hl[M_ * FF_];             // fc2_w split

// ---- f32x2 packed-FMA helpers ----
__device__ __forceinline__ u64 dup2(float x) {
    u64 r; asm("mov.b64 %0, {%1,%1};" : "=l"(r) : "f"(x)); return r;
}
__device__ __forceinline__ void fma2(u64& d, u64 a, u64 b) {
    asm("fma.rn.f32x2 %0, %1, %2, %0;" : "+l"(d) : "l"(a), "l"(b));
}
__device__ __forceinline__ float2 unpack2(u64 v) {
    float2 r; asm("mov.b64 {%0,%1}, %2;" : "=f"(r.x), "=f"(r.y) : "l"(v)); return r;
}

// ---- tf32 helpers ----
__device__ __forceinline__ uint32_t f2tf32(float x) {
    uint32_t r; asm("cvt.rna.tf32.f32 %0, %1;" : "=r"(r) : "f"(x)); return r;
}
__device__ __forceinline__ uint2 split_tf32(float x) {
    uint32_t hi = f2tf32(x);
    float lo = x - __uint_as_float(hi);
    return make_uint2(hi, __float_as_uint(lo));
}
__device__ __forceinline__ void mma_tf32(float* c,
    uint32_t a0, uint32_t a1, uint32_t a2, uint32_t a3,
    uint32_t b0, uint32_t b1)
{
    asm("mma.sync.aligned.m16n8k8.row.col.f32.tf32.tf32.f32 "
        "{%0,%1,%2,%3}, {%4,%5,%6,%7}, {%8,%9}, {%0,%1,%2,%3};"
        : "+f"(c[0]), "+f"(c[1]), "+f"(c[2]), "+f"(c[3])
        : "r"(a0), "r"(a1), "r"(a2), "r"(a3), "r"(b0), "r"(b1));
}

// ============================================================
// LayerNorm (fp32 out) — used for ln1
// ============================================================
__global__ void ln_kernel(const float* __restrict__ x,
                          const float* __restrict__ g,
                          const float* __restrict__ b,
                          float* __restrict__ out)
{
    int row = blockIdx.x;
    const float* xr = x + (size_t)row * M_;
    int t = threadIdx.x;
    float v = xr[t];

    __shared__ float sm[8];
    float s = v;
    #pragma unroll
    for (int o = 16; o > 0; o >>= 1) s += __shfl_xor_sync(0xffffffffu, s, o);
    if ((t & 31) == 0) sm[t >> 5] = s;
    __syncthreads();
    float mean = 0.f;
    #pragma unroll
    for (int i = 0; i < 8; i++) mean += sm[i];
    mean *= (1.0f / M_);
    __syncthreads();
    float d = v - mean;
    float q = d * d;
    #pragma unroll
    for (int o = 16; o > 0; o >>= 1) q += __shfl_xor_sync(0xffffffffu, q, o);
    if ((t & 31) == 0) sm[t >> 5] = q;
    __syncthreads();
    float var = 0.f;
    #pragma unroll
    for (int i = 0; i < 8; i++) var += sm[i];
    var *= (1.0f / M_);

    out[(size_t)row * M_ + t] = d * rsqrtf(var + 1e-5f) * g[t] + b[t];
}

// ============================================================
// LayerNorm writing split hi/lo (for ln2 -> fc1 input)
// ============================================================
__global__ void ln_hl_kernel(const float* __restrict__ x,
                             const float* __restrict__ g,
                             const float* __restrict__ b,
                             uint2* __restrict__ out)
{
    int row = blockIdx.x;
    const float* xr = x + (size_t)row * M_;
    int t = threadIdx.x;
    float v = xr[t];

    __shared__ float sm[8];
    float s = v;
    #pragma unroll
    for (int o = 16; o > 0; o >>= 1) s += __shfl_xor_sync(0xffffffffu, s, o);
    if ((t & 31) == 0) sm[t >> 5] = s;
    __syncthreads();
    float mean = 0.f;
    #pragma unroll
    for (int i = 0; i < 8; i++) mean += sm[i];
    mean *= (1.0f / M_);
    __syncthreads();
    float d = v - mean;
    float q = d * d;
    #pragma unroll
    for (int o = 16; o > 0; o >>= 1) q += __shfl_xor_sync(0xffffffffu, q, o);
    if ((t & 31) == 0) sm[t >> 5] = q;
    __syncthreads();
    float var = 0.f;
    #pragma unroll
    for (int i = 0; i < 8; i++) var += sm[i];
    var *= (1.0f / M_);

    float v2 = d * rsqrtf(var + 1e-5f) * g[t] + b[t];
    out[(size_t)row * M_ + t] = split_tf32(v2);
}

// ============================================================
// Weight convert: fp32 -> uint2{tf32hi, lo}
// ============================================================
__global__ void cvtw_kernel(const float* __restrict__ src, uint2* __restrict__ dst, int n)
{
    int i = blockIdx.x * 256 + threadIdx.x;
    if (i < n) dst[i] = split_tf32(src[i]);
}

// ============================================================
// Wo row sums
// ============================================================
__global__ void rowsum_kernel(const float* __restrict__ Wo, float* __restrict__ ws)
{
    int n = threadIdx.x;
    float s = 0.f;
    for (int m = 0; m < M_; m++) s += Wo[(size_t)n * M_ + m];
    ws[n] = s;
}

// ============================================================
// Gram: G = S^T S per slab, symmetry + f32x2 + double buffer
// ============================================================
__global__ void __launch_bounds__(256) gram_kernel(const float* __restrict__ sln,
                                                   float* __restrict__ G)
{
    if (blockIdx.y < blockIdx.x) return;
    int slab = blockIdx.z;
    const float* A = sln + (size_t)slab * J_ * M_;
    int p0 = blockIdx.x * 64, q0 = blockIdx.y * 64;

    __shared__ float As[2][16][64], Bs[2][16][64];
    int tid = threadIdx.x;
    int jj = tid >> 4;
    int cq = (tid & 15) << 2;
    int tx = tid & 15, ty = tid >> 4;

    const int NT = (J_ + 15) / 16;   // 65

    float4 av, bv;
    {
        int j = jj;
        if (j < J_) {
            av = *(const float4*)(A + (size_t)j * M_ + p0 + cq);
            bv = *(const float4*)(A + (size_t)j * M_ + q0 + cq);
        } else { av = make_float4(0.f,0.f,0.f,0.f); bv = av; }
    }
    *(float4*)&As[0][jj][cq] = av;
    *(float4*)&Bs[0][jj][cq] = bv;
    __syncthreads();

    u64 acc[4][2] = {};
    for (int it = 0; it < NT; it++) {
        int cur = it & 1;
        float4 nav, nbv;
        bool more = (it + 1 < NT);
        if (more) {
            int j = (it + 1) * 16 + jj;
            if (j < J_) {
                nav = *(const float4*)(A + (size_t)j * M_ + p0 + cq);
                nbv = *(const float4*)(A + (size_t)j * M_ + q0 + cq);
            } else { nav = make_float4(0.f,0.f,0.f,0.f); nbv = nav; }
        }
        #pragma unroll
        for (int k = 0; k < 16; k++) {
            float4 a = *(const float4*)&As[cur][k][ty << 2];
            ulonglong2 b = *(const ulonglong2*)&Bs[cur][k][tx << 2];
            u64 a2;
            a2 = dup2(a.x); fma2(acc[0][0], a2, b.x); fma2(acc[0][1], a2, b.y);
            a2 = dup2(a.y); fma2(acc[1][0], a2, b.x); fma2(acc[1][1], a2, b.y);
            a2 = dup2(a.z); fma2(acc[2][0], a2, b.x); fma2(acc[2][1], a2, b.y);
            a2 = dup2(a.w); fma2(acc[3][0], a2, b.x); fma2(acc[3][1], a2, b.y);
        }
        if (more) {
            *(float4*)&As[cur ^ 1][jj][cq] = nav;
            *(float4*)&Bs[cur ^ 1][jj][cq] = nbv;
        }
        __syncthreads();
    }
    float* Gs = G + (size_t)slab * M_ * M_;
    #pragma unroll
    for (int i = 0; i < 4; i++) {
        int p = p0 + (ty << 2) + i;
        #pragma unroll
        for (int j2 = 0; j2 < 2; j2++) {
            float2 v = unpack2(acc[i][j2]);
            int q = q0 + (tx << 2) + j2 * 2;
            Gs[(size_t)p * M_ + q]     = v.x;
            Gs[(size_t)p * M_ + q + 1] = v.y;
            Gs[(size_t)q * M_ + p]       = v.x;
            Gs[(size_t)(q + 1) * M_ + p] = v.y;
        }
    }
}

// ============================================================
// 64x64 NT GEMM (T = G @ Wv^T)
// ============================================================
__global__ void __launch_bounds__(256) gemm64(
    const float* __restrict__ Ab, int lda, long aStride,
    const float* __restrict__ Bb, int ldb, long bStride,
    float* __restrict__ Cb, int ldc, long cStride, int K)
{
    int slab = blockIdx.z;
    const float* A = Ab + (size_t)slab * aStride;
    const float* B = Bb + (size_t)slab * bStride;
    float*       C = Cb + (size_t)slab * cStride;

    int rowBase = blockIdx.x * 64;
    int colBase = blockIdx.y * 64;

    __shared__ float As[16][64], Bs[16][64];
    int tid = threadIdx.x;
    int lm = tid >> 2;
    int lk = (tid & 3) << 2;
    int tx = tid & 15, ty = tid >> 4;

    u64 acc[4][2] = {};
    for (int k0 = 0; k0 < K; k0 += 16) {
        float4 av = *(const float4*)(A + (size_t)(rowBase + lm) * lda + k0 + lk);
        As[lk + 0][lm] = av.x; As[lk + 1][lm] = av.y;
        As[lk + 2][lm] = av.z; As[lk + 3][lm] = av.w;
        float4 bv = *(const float4*)(B + (size_t)(colBase + lm) * ldb + k0 + lk);
        Bs[lk + 0][lm] = bv.x; Bs[lk + 1][lm] = bv.y;
        Bs[lk + 2][lm] = bv.z; Bs[lk + 3][lm] = bv.w;
        __syncthreads();
        #pragma unroll
        for (int k = 0; k < 16; k++) {
            float4 a = *(const float4*)&As[k][ty << 2];
            ulonglong2 b = *(const ulonglong2*)&Bs[k][tx << 2];
            u64 a2;
            a2 = dup2(a.x); fma2(acc[0][0], a2, b.x); fma2(acc[0][1], a2, b.y);
            a2 = dup2(a.y); fma2(acc[1][0], a2, b.x); fma2(acc[1][1], a2, b.y);
            a2 = dup2(a.z); fma2(acc[2][0], a2, b.x); fma2(acc[2][1], a2, b.y);
            a2 = dup2(a.w); fma2(acc[3][0], a2, b.x); fma2(acc[3][1], a2, b.y);
        }
        __syncthreads();
    }
    #pragma unroll
    for (int i = 0; i < 4; i++) {
        int r = rowBase + (ty << 2) + i;
        #pragma unroll
        for (int j2 = 0; j2 < 2; j2++) {
            int c = colBase + (tx << 2) + j2 * 2;
            float2 v = unpack2(acc[i][j2]);
            *(float2*)(C + (size_t)r * ldc + c) = v;
        }
    }
}

// ============================================================
// Small per-(head,slab) finisher
// ============================================================
__global__ void __launch_bounds__(256) assemble2_kernel(const float* __restrict__ Wqkv,
                                                        const float* __restrict__ T,
                                                        float* __restrict__ ET)
{
    int h = blockIdx.x;
    int slab = blockIdx.y;
    const float* Ts = T + (size_t)slab * M_ * M_;
    const float* Wq = Wqkv + (size_t)(0 * H_ + h) * DH_ * M_;
    const float* Wk = Wqkv + (size_t)(1 * H_ + h) * DH_ * M_;

    __shared__ float sT[256][33];
    __shared__ float ktv[32][33];
    int tid = threadIdx.x;

    {
        int m = tid >> 5, d = tid & 31;
        #pragma unroll
        for (int pass = 0; pass < 32; pass++) {
            int mm = pass * 8 + m;
            sT[mm][d] = Ts[(size_t)mm * M_ + h * 32 + d];
        }
    }
    __syncthreads();

    {
        int d  = tid & 31;
        int e0 = (tid >> 5) << 2;
        float acc4[4] = {0.f, 0.f, 0.f, 0.f};
        for (int m = 0; m < 256; m++) {
            float t = sT[m][d];
            #pragma unroll
            for (int ee = 0; ee < 4; ee++)
                acc4[ee] = fmaf(Wk[(size_t)(e0 + ee) * M_ + m], t, acc4[ee]);
        }
        #pragma unroll
        for (int ee = 0; ee < 4; ee++)
            ktv[e0 + ee][d] = acc4[ee];
    }
    __syncthreads();

    float acc3[32];
    #pragma unroll
    for (int d = 0; d < 32; d++) acc3[d] = 0.f;
    for (int e2 = 0; e2 < 32; e2++) {
        float w = Wq[(size_t)e2 * M_ + tid];
        #pragma unroll
        for (int d = 0; d < 32; d++) acc3[d] = fmaf(w, ktv[e2][d], acc3[d]);
    }
    const float scale = 0.17677669529663687f;
    float* ETs = ET + (size_t)slab * M_ * M_;
    #pragma unroll
    for (int d = 0; d < 32; d++)
        ETs[(size_t)(h * 32 + d) * M_ + tid] = scale * acc3[d];
}

// ============================================================
// 128x128 NT fp32 GEMM, f32x2, double-buffered (s2 only).
// ============================================================
__global__ void __launch_bounds__(256) gemm128(
    const float* __restrict__ Ab, int lda, long aStride,
    const float* __restrict__ Bb, int ldb, long bStride,
    float* __restrict__ Cb, int ldc, long cStride,
    int K, int Rlim,
    const float* __restrict__ e1,
    const float* __restrict__ e2, long e2Stride)
{
    int slab = blockIdx.z;
    const float* A = Ab + (size_t)slab * aStride;
    const float* B = Bb + (size_t)slab * bStride;
    float*       C = Cb + (size_t)slab * cStride;
    const float* E2 = e2 + (size_t)slab * e2Stride;

    int rowBase = blockIdx.x * 128;
    int colBase = blockIdx.y * 128;

    __shared__ float As[2][16][128], Bs[2][16][128];
    int tid = threadIdx.x;
    int ldRow = tid >> 1;
    int ldK   = (tid & 1) << 3;
    int tx = tid & 15, ty = tid >> 4;
    int tx4 = tx << 2, ty4 = ty << 2;

    const float* Arow = A + (size_t)(rowBase + ldRow) * lda + ldK;
    const float* Brow = B + (size_t)(colBase + ldRow) * ldb + ldK;
    bool aValid = (rowBase + ldRow) < Rlim;

    const int NT = K >> 4;

    {
        float4 av0, av1;
        if (aValid) { av0 = *(const float4*)Arow; av1 = *(const float4*)(Arow + 4); }
        else        { av0 = make_float4(0.f,0.f,0.f,0.f); av1 = av0; }
        float4 bv0 = *(const float4*)Brow;
        float4 bv1 = *(const float4*)(Brow + 4);
        As[0][ldK+0][ldRow]=av0.x; As[0][ldK+1][ldRow]=av0.y;
        As[0][ldK+2][ldRow]=av0.z; As[0][ldK+3][ldRow]=av0.w;
        As[0][ldK+4][ldRow]=av1.x; As[0][ldK+5][ldRow]=av1.y;
        As[0][ldK+6][ldRow]=av1.z; As[0][ldK+7][ldRow]=av1.w;
        Bs[0][ldK+0][ldRow]=bv0.x; Bs[0][ldK+1][ldRow]=bv0.y;
        Bs[0][ldK+2][ldRow]=bv0.z; Bs[0][ldK+3][ldRow]=bv0.w;
        Bs[0][ldK+4][ldRow]=bv1.x; Bs[0][ldK+5][ldRow]=bv1.y;
        Bs[0][ldK+6][ldRow]=bv1.z; Bs[0][ldK+7][ldRow]=bv1.w;
    }
    __syncthreads();

    u64 acc[8][4] = {};
    for (int it = 0; it < NT; it++) {
        int cur = it & 1;
        bool more = (it + 1 < NT);
        float4 nav0, nav1, nbv0, nbv1;
        if (more) {
            int k0 = (it + 1) << 4;
            if (aValid) { nav0 = *(const float4*)(Arow + k0); nav1 = *(const float4*)(Arow + k0 + 4); }
            else        { nav0 = make_float4(0.f,0.f,0.f,0.f); nav1 = nav0; }
            nbv0 = *(const float4*)(Brow + k0);
            nbv1 = *(const float4*)(Brow + k0 + 4);
        }

        #pragma unroll
        for (int k = 0; k < 16; k++) {
            float4 a0 = *(const float4*)&As[cur][k][ty4];
            float4 a1 = *(const float4*)&As[cur][k][ty4 + 64];
            ulonglong2 b0 = *(const ulonglong2*)&Bs[cur][k][tx4];
            ulonglong2 b1 = *(const ulonglong2*)&Bs[cur][k][tx4 + 64];
            u64 a2;
            a2 = dup2(a0.x); fma2(acc[0][0],a2,b0.x); fma2(acc[0][1],a2,b0.y); fma2(acc[0][2],a2,b1.x); fma2(acc[0][3],a2,b1.y);
            a2 = dup2(a0.y); fma2(acc[1][0],a2,b0.x); fma2(acc[1][1],a2,b0.y); fma2(acc[1][2],a2,b1.x); fma2(acc[1][3],a2,b1.y);
            a2 = dup2(a0.z); fma2(acc[2][0],a2,b0.x); fma2(acc[2][1],a2,b0.y); fma2(acc[2][2],a2,b1.x); fma2(acc[2][3],a2,b1.y);
            a2 = dup2(a0.w); fma2(acc[3][0],a2,b0.x); fma2(acc[3][1],a2,b0.y); fma2(acc[3][2],a2,b1.x); fma2(acc[3][3],a2,b1.y);
            a2 = dup2(a1.x); fma2(acc[4][0],a2,b0.x); fma2(acc[4][1],a2,b0.y); fma2(acc[4][2],a2,b1.x); fma2(acc[4][3],a2,b1.y);
            a2 = dup2(a1.y); fma2(acc[5][0],a2,b0.x); fma2(acc[5][1],a2,b0.y); fma2(acc[5][2],a2,b1.x); fma2(acc[5][3],a2,b1.y);
            a2 = dup2(a1.z); fma2(acc[6][0],a2,b0.x); fma2(acc[6][1],a2,b0.y); fma2(acc[6][2],a2,b1.x); fma2(acc[6][3],a2,b1.y);
            a2 = dup2(a1.w); fma2(acc[7][0],a2,b0.x); fma2(acc[7][1],a2,b0.y); fma2(acc[7][2],a2,b1.x); fma2(acc[7][3],a2,b1.y);
        }

        if (more) {
            int nxt = cur ^ 1;
            As[nxt][ldK+0][ldRow]=nav0.x; As[nxt][ldK+1][ldRow]=nav0.y;
            As[nxt][ldK+2][ldRow]=nav0.z; As[nxt][ldK+3][ldRow]=nav0.w;
            As[nxt][ldK+4][ldRow]=nav1.x; As[nxt][ldK+5][ldRow]=nav1.y;
            As[nxt][ldK+6][ldRow]=nav1.z; As[nxt][ldK+7][ldRow]=nav1.w;
            Bs[nxt][ldK+0][ldRow]=nbv0.x; Bs[nxt][ldK+1][ldRow]=nbv0.y;
            Bs[nxt][ldK+2][ldRow]=nbv0.z; Bs[nxt][ldK+3][ldRow]=nbv0.w;
            Bs[nxt][ldK+4][ldRow]=nbv1.x; Bs[nxt][ldK+5][ldRow]=nbv1.y;
            Bs[nxt][ldK+6][ldRow]=nbv1.z; Bs[nxt][ldK+7][ldRow]=nbv1.w;
        }
        __syncthreads();
    }

    #pragma unroll
    for (int i = 0; i < 8; i++) {
        int r = rowBase + ty4 + (i & 3) + ((i >> 2) << 6);
        if (r >= Rlim) continue;
        #pragma unroll
        for (int j2 = 0; j2 < 4; j2++) {
            int c = colBase + tx4 + ((j2 & 1) << 1) + ((j2 >> 1) << 6);
            float2 v = unpack2(acc[i][j2]);
            size_t idx = (size_t)r * ldc + c;
            v.x = v.x * e1[c]     + E2[idx];
            v.y = v.y * e1[c + 1] + E2[idx + 1];
            *(float2*)(C + idx) = v;
        }
    }
}

// ============================================================
// 3xTF32 tensor-core NT GEMM on PRE-SPLIT uint2{hi,lo} inputs.
// 128x128 CTA, 8 warps (2x4), 64x32 per warp, m16n8k8.
//   mode 1: gelu(acc + bias[c]) -> uint2 hi/lo output (Ch)
//   mode 2: acc + bias[c] + resid[r,c] -> fp32 output (Cf)
// ============================================================
#define SU 18   // smem row stride in uint2 (16 + 2 pad)
__global__ void __launch_bounds__(256) tf32_gemm(
    const uint2* __restrict__ A, int lda,
    const uint2* __restrict__ B, int ldb,
    int K, int Rlim, int mode, int ldc,
    const float* __restrict__ bias,
    const float* __restrict__ resid,
    float* __restrict__ Cf,
    uint2* __restrict__ Ch)
{
    extern __shared__ __align__(16) uint2 dsm[];
    // layout: As[2][128*SU], Bs[2][128*SU]
    uint2* AsBuf[2] = { dsm, dsm + 128 * SU };
    uint2* BsBuf[2] = { dsm + 2 * 128 * SU, dsm + 3 * 128 * SU };

    int tid = threadIdx.x;
    int rowBase = blockIdx.x * 128, colBase = blockIdx.y * 128;

    int ldRow = tid >> 1;            // 0..127
    int ldK   = (tid & 1) << 3;      // 0 or 8
    const uint2* Arow = A + (size_t)(rowBase + ldRow) * lda + ldK;
    const uint2* Brow = B + (size_t)(colBase + ldRow) * ldb + ldK;
    bool aValid = (rowBase + ldRow) < Rlim;

    int lane = tid & 31, warp = tid >> 5;
    int wRow = (warp >> 2) << 6;     // 0 or 64
    int wCol = (warp & 3) << 5;      // 0,32,64,96
    int g = lane >> 2, t = lane & 3;

    const int NT = K >> 4;
    const uint4 z4 = make_uint4(0u, 0u, 0u, 0u);

    // preload tile 0
    {
        uint2* pa = AsBuf[0] + ldRow * SU + ldK;
        uint2* pb = BsBuf[0] + ldRow * SU + ldK;
        #pragma unroll
        for (int j = 0; j < 4; j++) {
            uint4 va = aValid ? *(const uint4*)(Arow + 2 * j) : z4;
            *(uint4*)(pa + 2 * j) = va;
            uint4 vb = *(const uint4*)(Brow + 2 * j);
            *(uint4*)(pb + 2 * j) = vb;
        }
    }
    __syncthreads();

    float acc[4][4][4];
    #pragma unroll
    for (int i = 0; i < 4; i++)
        #pragma unroll
        for (int j = 0; j < 4; j++)
            #pragma unroll
            for (int q = 0; q < 4; q++) acc[i][j][q] = 0.f;

    for (int it = 0; it < NT; it++) {
        int cur = it & 1;
        bool more = (it + 1 < NT);
        uint4 nva[4], nvb[4];
        if (more) {
            int k0 = (it + 1) << 4;
            #pragma unroll
            for (int j = 0; j < 4; j++) {
                nva[j] = aValid ? *(const uint4*)(Arow + k0 + 2 * j) : z4;
                nvb[j] = *(const uint4*)(Brow + k0 + 2 * j);
            }
        }

        const uint2* sa = AsBuf[cur];
        const uint2* sb = BsBuf[cur];
        #pragma unroll
        for (int ks = 0; ks < 2; ks++) {
            int kk = (ks << 3) + t;
            uint2 af[4][4];
            #pragma unroll
            for (int mb = 0; mb < 4; mb++) {
                int rb = wRow + (mb << 4);
                af[mb][0] = sa[(rb + g)     * SU + kk];
                af[mb][1] = sa[(rb + g + 8) * SU + kk];
                af[mb][2] = sa[(rb + g)     * SU + kk + 4];
                af[mb][3] = sa[(rb + g + 8) * SU + kk + 4];
            }
            uint2 bf[4][2];
            #pragma unroll
            for (int nb = 0; nb < 4; nb++) {
                int cb = wCol + (nb << 3);
                bf[nb][0] = sb[(cb + g) * SU + kk];
                bf[nb][1] = sb[(cb + g) * SU + kk + 4];
            }
            // ah*bl
            #pragma unroll
            for (int mb = 0; mb < 4; mb++)
                #pragma unroll
                for (int nb = 0; nb < 4; nb++)
                    mma_tf32(acc[mb][nb], af[mb][0].x, af[mb][1].x, af[mb][2].x, af[mb][3].x,
                             bf[nb][0].y, bf[nb][1].y);
            // al*bh
            #pragma unroll
            for (int mb = 0; mb < 4; mb++)
                #pragma unroll
                for (int nb = 0; nb < 4; nb++)
                    mma_tf32(acc[mb][nb], af[mb][0].y, af[mb][1].y, af[mb][2].y, af[mb][3].y,
                             bf[nb][0].x, bf[nb][1].x);
            // ah*bh
            #pragma unroll
            for (int mb = 0; mb < 4; mb++)
                #pragma unroll
                for (int nb = 0; nb < 4; nb++)
                    mma_tf32(acc[mb][nb], af[mb][0].x, af[mb][1].x, af[mb][2].x, af[mb][3].x,
                             bf[nb][0].x, bf[nb][1].x);
        }

        if (more) {
            int nxt = cur ^ 1;
            uint2* pa = AsBuf[nxt] + ldRow * SU + ldK;
            uint2* pb = BsBuf[nxt] + ldRow * SU + ldK;
            #pragma unroll
            for (int j = 0; j < 4; j++) {
                *(uint4*)(pa + 2 * j) = nva[j];
                *(uint4*)(pb + 2 * j) = nvb[j];
            }
        }
        __syncthreads();
    }

    // epilogue
    const float inv_sqrt2 = 0.7071067811865475f;
    #pragma unroll
    for (int mb = 0; mb < 4; mb++) {
        int r0 = rowBase + wRow + (mb << 4) + g;
        #pragma unroll
        for (int half = 0; half < 2; half++) {
            int r = r0 + half * 8;
            if (r >= Rlim) continue;
            #pragma unroll
            for (int nb = 0; nb < 4; nb++) {
                int c = colBase + wCol + (nb << 3) + (t << 1);
                float vx = acc[mb][nb][half * 2 + 0];
                float vy = acc[mb][nb][half * 2 + 1];
                if (mode == 1) {
                    vx += bias[c];
                    vy += bias[c + 1];
                    vx = 0.5f * vx * (1.0f + erff(vx * inv_sqrt2));
                    vy = 0.5f * vy * (1.0f + erff(vy * inv_sqrt2));
                    uint2 hx = split_tf32(vx);
                    uint2 hy = split_tf32(vy);
                    *(uint4*)(Ch + (size_t)r * ldc + c) = make_uint4(hx.x, hx.y, hy.x, hy.y);
                } else {
                    const float* rr = resid + (size_t)r * ldc + c;
                    vx += bias[c]     + rr[0];
                    vy += bias[c + 1] + rr[1];
                    *(float2*)(Cf + (size_t)r * ldc + c) = make_float2(vx, vy);
                }
            }
        }
    }
}

// ============================================================
// Launch
// ============================================================
extern "C" void kernel_launch(void* const* d_in, const int* in_sizes, int n_in,
                              void* d_out, int out_size)
{
    (void)in_sizes; (void)n_in; (void)out_size;
    const float* savespace = (const float*)d_in[1];
    const float* Wqkv      = (const float*)d_in[2];
    const float* Wo        = (const float*)d_in[3];
    const float* ln1_g     = (const float*)d_in[4];
    const float* ln1_b     = (const float*)d_in[5];
    const float* ln2_g     = (const float*)d_in[6];
    const float* ln2_b     = (const float*)d_in[7];
    const float* fc1_w     = (const float*)d_in[8];
    const float* fc1_b     = (const float*)d_in[9];
    const float* fc2_w     = (const float*)d_in[10];
    const float* fc2_b     = (const float*)d_in[11];
    float* out = (float*)d_out;

    float *p_sln, *p_s2, *p_G, *p_T, *p_ET, *p_ws;
    uint2 *p_hln2, *p_h1hl, *p_w1hl, *p_w2hl;
    cudaGetSymbolAddress((void**)&p_sln, g_sln);
    cudaGetSymbolAddress((void**)&p_s2,  g_s2);
    cudaGetSymbolAddress((void**)&p_G,   g_G);
    cudaGetSymbolAddress((void**)&p_T,   g_T);
    cudaGetSymbolAddress((void**)&p_ET,  g_ET);
    cudaGetSymbolAddress((void**)&p_ws,  g_wosum);
    cudaGetSymbolAddress((void**)&p_hln2, g_hln2);
    cudaGetSymbolAddress((void**)&p_h1hl, g_h1hl);
    cudaGetSymbolAddress((void**)&p_w1hl, g_w1hl);
    cudaGetSymbolAddress((void**)&p_w2hl, g_w2hl);

    const long SLAB = (long)J_ * M_;
    const long MM   = (long)M_ * M_;
    const int TSMEM = 4 * 128 * SU * 8;   // 73728 bytes
    static int smemSet = 0;
    if (!smemSet) {
        cudaFuncSetAttribute(tf32_gemm, cudaFuncAttributeMaxDynamicSharedMemorySize, TSMEM);
        smemSet = 1;
    }

    // 1) layernorm1
    ln_kernel<<<RTOT, 256>>>(savespace, ln1_g, ln1_b, p_sln);
    // 2) weight splits (independent)
    cvtw_kernel<<<(FF_ * M_ + 255) / 256, 256>>>(fc1_w, p_w1hl, FF_ * M_);
    cvtw_kernel<<<(M_ * FF_ + 255) / 256, 256>>>(fc2_w, p_w2hl, M_ * FF_);
    // 3) Gram per slab
    gram_kernel<<<dim3(4, 4, NSLAB), 256>>>(p_sln, p_G);
    // 4) Wo row sums
    rowsum_kernel<<<1, 256>>>(Wo, p_ws);
    // 5) T = G @ Wv_full^T per slab
    gemm64<<<dim3(4, 4, NSLAB), 256>>>(
        p_G, M_, MM,  Wqkv + 2 * H_ * DH_ * M_, M_, 0,  p_T, M_, MM, M_);
    // 6) finish ET per (head, slab)
    assemble2_kernel<<<dim3(H_, NSLAB), 256>>>(Wqkv, p_T, p_ET);
    // 7) s2 = wosum * (s_ln @ E) + savespace
    gemm128<<<dim3(9, 2, NSLAB), 256>>>(
        p_sln, M_, SLAB,  p_ET, M_, MM,  p_s2, M_, SLAB,
        M_, J_, p_ws, savespace, SLAB);
    // 8) layernorm2 -> split hi/lo
    ln_hl_kernel<<<RTOT, 256>>>(p_s2, ln2_g, ln2_b, p_hln2);
    // 9) h1 = gelu(hln @ fc1_w^T + b1)   [pre-split 3xTF32]
    tf32_gemm<<<dim3(129, 8), 256, TSMEM>>>(
        p_hln2, M_, p_w1hl, M_,
        M_, RTOT, 1, FF_, fc1_b, (const float*)0, (float*)0, p_h1hl);
    // 10) out = h1 @ fc2_w^T + b2 + s2   [pre-split 3xTF32]
    tf32_gemm<<<dim3(129, 2), 256, TSMEM>>>(
        p_h1hl, FF_, p_w2hl, FF_,
        FF_, RTOT, 2, M_, fc2_b, p_s2, out, (uint2*)0);
}

// round 8
// speedup vs baseline: 1.1528x; 1.1528x over previous
#include <cuda_runtime.h>
#include <math.h>
#include <cstdint>

// Shapes (fixed by the problem)
#define B_    2
#define I_    8
#define J_    1025
#define M_    256
#define H_    8
#define DH_   32
#define NSLAB 16              // B_*I_
#define RTOT  (NSLAB * J_)    // 16400
#define FF_   1024            // 4*M
#define NCH   5               // gram J-chunks
#define MM_   (M_ * M_)

typedef unsigned long long u64;

// ---- scratch (static __device__ arrays; no runtime allocation) ----
__device__ float g_sln[RTOT * M_];
__device__ float g_s2 [RTOT * M_];
__device__ float g_hln[RTOT * M_];
__device__ float g_h1 [(size_t)RTOT * FF_];
__device__ float g_G  [NSLAB * MM_];
__device__ float g_Gp [NCH * NSLAB * MM_];     // gram partials
__device__ float g_T  [NSLAB * MM_];
__device__ float g_ET [NSLAB * MM_];
__device__ float g_wosum[M_];

// ---- f32x2 packed-FMA helpers ----
__device__ __forceinline__ u64 dup2(float x) {
    u64 r; asm("mov.b64 %0, {%1,%1};" : "=l"(r) : "f"(x)); return r;
}
__device__ __forceinline__ void fma2(u64& d, u64 a, u64 b) {
    asm("fma.rn.f32x2 %0, %1, %2, %0;" : "+l"(d) : "l"(a), "l"(b));
}
__device__ __forceinline__ float2 unpack2(u64 v) {
    float2 r; asm("mov.b64 {%0,%1}, %2;" : "=f"(r.x), "=f"(r.y) : "l"(v)); return r;
}

// ---- tf32 helpers ----
__device__ __forceinline__ uint32_t f2tf32(float x) {
    uint32_t r; asm("cvt.rna.tf32.f32 %0, %1;" : "=r"(r) : "f"(x)); return r;
}
__device__ __forceinline__ uint2 split_tf32(float x) {
    uint32_t hi = f2tf32(x);
    float lo = x - __uint_as_float(hi);
    return make_uint2(hi, __float_as_uint(lo));
}
__device__ __forceinline__ void mma_tf32(float* c,
    uint32_t a0, uint32_t a1, uint32_t a2, uint32_t a3,
    uint32_t b0, uint32_t b1)
{
    asm("mma.sync.aligned.m16n8k8.row.col.f32.tf32.tf32.f32 "
        "{%0,%1,%2,%3}, {%4,%5,%6,%7}, {%8,%9}, {%0,%1,%2,%3};"
        : "+f"(c[0]), "+f"(c[1]), "+f"(c[2]), "+f"(c[3])
        : "r"(a0), "r"(a1), "r"(a2), "r"(a3), "r"(b0), "r"(b1));
}

// ============================================================
// LayerNorm over last dim M_=256, one block (256 thr) per row
// ============================================================
__global__ void ln_kernel(const float* __restrict__ x,
                          const float* __restrict__ g,
                          const float* __restrict__ b,
                          float* __restrict__ out)
{
    int row = blockIdx.x;
    const float* xr = x + (size_t)row * M_;
    int t = threadIdx.x;
    float v = xr[t];

    __shared__ float sm[8];
    float s = v;
    #pragma unroll
    for (int o = 16; o > 0; o >>= 1) s += __shfl_xor_sync(0xffffffffu, s, o);
    if ((t & 31) == 0) sm[t >> 5] = s;
    __syncthreads();
    float mean = 0.f;
    #pragma unroll
    for (int i = 0; i < 8; i++) mean += sm[i];
    mean *= (1.0f / M_);
    __syncthreads();
    float d = v - mean;
    float q = d * d;
    #pragma unroll
    for (int o = 16; o > 0; o >>= 1) q += __shfl_xor_sync(0xffffffffu, q, o);
    if ((t & 31) == 0) sm[t >> 5] = q;
    __syncthreads();
    float var = 0.f;
    #pragma unroll
    for (int i = 0; i < 8; i++) var += sm[i];
    var *= (1.0f / M_);

    out[(size_t)row * M_ + t] = d * rsqrtf(var + 1e-5f) * g[t] + b[t];
}

// ============================================================
// Wo row sums
// ============================================================
__global__ void rowsum_kernel(const float* __restrict__ Wo, float* __restrict__ ws)
{
    int n = threadIdx.x;
    float s = 0.f;
    for (int m = 0; m < M_; m++) s += Wo[(size_t)n * M_ + m];
    ws[n] = s;
}

// ============================================================
// Gram partials: Gp[slab,ch] = S_chunk^T S_chunk, J split in NCH
// chunks of 13 16-row tiles each. Symmetric blocks mirrored.
// ============================================================
__global__ void __launch_bounds__(256) gram_kernel(const float* __restrict__ sln,
                                                   float* __restrict__ Gp)
{
    if (blockIdx.y < blockIdx.x) return;
    int zc = blockIdx.z;
    int slab = zc / NCH;
    int ch = zc - slab * NCH;
    const float* A = sln + (size_t)slab * J_ * M_;
    int p0 = blockIdx.x * 64, q0 = blockIdx.y * 64;

    int t0 = ch * 13, t1 = t0 + 13;   // 65 tiles total = 5*13

    __shared__ float As[2][16][64], Bs[2][16][64];
    int tid = threadIdx.x;
    int jj = tid >> 4;
    int cq = (tid & 15) << 2;
    int tx = tid & 15, ty = tid >> 4;

    float4 av, bv;
    {
        int j = t0 * 16 + jj;
        if (j < J_) {
            av = *(const float4*)(A + (size_t)j * M_ + p0 + cq);
            bv = *(const float4*)(A + (size_t)j * M_ + q0 + cq);
        } else { av = make_float4(0.f,0.f,0.f,0.f); bv = av; }
    }
    *(float4*)&As[0][jj][cq] = av;
    *(float4*)&Bs[0][jj][cq] = bv;
    __syncthreads();

    u64 acc[4][2] = {};
    for (int it = t0; it < t1; it++) {
        int cur = (it - t0) & 1;
        float4 nav, nbv;
        bool more = (it + 1 < t1);
        if (more) {
            int j = (it + 1) * 16 + jj;
            if (j < J_) {
                nav = *(const float4*)(A + (size_t)j * M_ + p0 + cq);
                nbv = *(const float4*)(A + (size_t)j * M_ + q0 + cq);
            } else { nav = make_float4(0.f,0.f,0.f,0.f); nbv = nav; }
        }
        #pragma unroll
        for (int k = 0; k < 16; k++) {
            float4 a = *(const float4*)&As[cur][k][ty << 2];
            ulonglong2 b = *(const ulonglong2*)&Bs[cur][k][tx << 2];
            u64 a2;
            a2 = dup2(a.x); fma2(acc[0][0], a2, b.x); fma2(acc[0][1], a2, b.y);
            a2 = dup2(a.y); fma2(acc[1][0], a2, b.x); fma2(acc[1][1], a2, b.y);
            a2 = dup2(a.z); fma2(acc[2][0], a2, b.x); fma2(acc[2][1], a2, b.y);
            a2 = dup2(a.w); fma2(acc[3][0], a2, b.x); fma2(acc[3][1], a2, b.y);
        }
        if (more) {
            *(float4*)&As[cur ^ 1][jj][cq] = nav;
            *(float4*)&Bs[cur ^ 1][jj][cq] = nbv;
        }
        __syncthreads();
    }
    float* Gs = Gp + (size_t)zc * MM_;
    #pragma unroll
    for (int i = 0; i < 4; i++) {
        int p = p0 + (ty << 2) + i;
        #pragma unroll
        for (int j2 = 0; j2 < 2; j2++) {
            float2 v = unpack2(acc[i][j2]);
            int q = q0 + (tx << 2) + j2 * 2;
            Gs[(size_t)p * M_ + q]     = v.x;
            Gs[(size_t)p * M_ + q + 1] = v.y;
            Gs[(size_t)q * M_ + p]       = v.x;
            Gs[(size_t)(q + 1) * M_ + p] = v.y;
        }
    }
}

// ============================================================
// Gram reduce: G[slab] = sum_ch Gp[slab,ch]
// ============================================================
__global__ void gram_reduce(const float* __restrict__ Gp, float* __restrict__ G)
{
    int slab = blockIdx.y;
    int idx = (blockIdx.x * 256 + threadIdx.x) * 4;
    const float* base = Gp + (size_t)slab * NCH * MM_ + idx;
    float4 s = *(const float4*)base;
    #pragma unroll
    for (int ch = 1; ch < NCH; ch++) {
        float4 v = *(const float4*)(base + (size_t)ch * MM_);
        s.x += v.x; s.y += v.y; s.z += v.z; s.w += v.w;
    }
    *(float4*)(G + (size_t)slab * MM_ + idx) = s;
}

// ============================================================
// 64x64 NT GEMM (T = G @ Wv^T)
// ============================================================
__global__ void __launch_bounds__(256) gemm64(
    const float* __restrict__ Ab, int lda, long aStride,
    const float* __restrict__ Bb, int ldb, long bStride,
    float* __restrict__ Cb, int ldc, long cStride, int K)
{
    int slab = blockIdx.z;
    const float* A = Ab + (size_t)slab * aStride;
    const float* B = Bb + (size_t)slab * bStride;
    float*       C = Cb + (size_t)slab * cStride;

    int rowBase = blockIdx.x * 64;
    int colBase = blockIdx.y * 64;

    __shared__ float As[16][64], Bs[16][64];
    int tid = threadIdx.x;
    int lm = tid >> 2;
    int lk = (tid & 3) << 2;
    int tx = tid & 15, ty = tid >> 4;

    u64 acc[4][2] = {};
    for (int k0 = 0; k0 < K; k0 += 16) {
        float4 av = *(const float4*)(A + (size_t)(rowBase + lm) * lda + k0 + lk);
        As[lk + 0][lm] = av.x; As[lk + 1][lm] = av.y;
        As[lk + 2][lm] = av.z; As[lk + 3][lm] = av.w;
        float4 bv = *(const float4*)(B + (size_t)(colBase + lm) * ldb + k0 + lk);
        Bs[lk + 0][lm] = bv.x; Bs[lk + 1][lm] = bv.y;
        Bs[lk + 2][lm] = bv.z; Bs[lk + 3][lm] = bv.w;
        __syncthreads();
        #pragma unroll
        for (int k = 0; k < 16; k++) {
            float4 a = *(const float4*)&As[k][ty << 2];
            ulonglong2 b = *(const ulonglong2*)&Bs[k][tx << 2];
            u64 a2;
            a2 = dup2(a.x); fma2(acc[0][0], a2, b.x); fma2(acc[0][1], a2, b.y);
            a2 = dup2(a.y); fma2(acc[1][0], a2, b.x); fma2(acc[1][1], a2, b.y);
            a2 = dup2(a.z); fma2(acc[2][0], a2, b.x); fma2(acc[2][1], a2, b.y);
            a2 = dup2(a.w); fma2(acc[3][0], a2, b.x); fma2(acc[3][1], a2, b.y);
        }
        __syncthreads();
    }
    #pragma unroll
    for (int i = 0; i < 4; i++) {
        int r = rowBase + (ty << 2) + i;
        #pragma unroll
        for (int j2 = 0; j2 < 2; j2++) {
            int c = colBase + (tx << 2) + j2 * 2;
            float2 v = unpack2(acc[i][j2]);
            *(float2*)(C + (size_t)r * ldc + c) = v;
        }
    }
}

// ============================================================
// Small per-(head,slab) finisher
// ============================================================
__global__ void __launch_bounds__(256) assemble2_kernel(const float* __restrict__ Wqkv,
                                                        const float* __restrict__ T,
                                                        float* __restrict__ ET)
{
    int h = blockIdx.x;
    int slab = blockIdx.y;
    const float* Ts = T + (size_t)slab * MM_;
    const float* Wq = Wqkv + (size_t)(0 * H_ + h) * DH_ * M_;
    const float* Wk = Wqkv + (size_t)(1 * H_ + h) * DH_ * M_;

    __shared__ float sT[256][33];
    __shared__ float ktv[32][33];
    int tid = threadIdx.x;

    {
        int m = tid >> 5, d = tid & 31;
        #pragma unroll
        for (int pass = 0; pass < 32; pass++) {
            int mm = pass * 8 + m;
            sT[mm][d] = Ts[(size_t)mm * M_ + h * 32 + d];
        }
    }
    __syncthreads();

    {
        int d  = tid & 31;
        int e0 = (tid >> 5) << 2;
        float acc4[4] = {0.f, 0.f, 0.f, 0.f};
        for (int m = 0; m < 256; m++) {
            float t = sT[m][d];
            #pragma unroll
            for (int ee = 0; ee < 4; ee++)
                acc4[ee] = fmaf(Wk[(size_t)(e0 + ee) * M_ + m], t, acc4[ee]);
        }
        #pragma unroll
        for (int ee = 0; ee < 4; ee++)
            ktv[e0 + ee][d] = acc4[ee];
    }
    __syncthreads();

    float acc3[32];
    #pragma unroll
    for (int d = 0; d < 32; d++) acc3[d] = 0.f;
    for (int e2 = 0; e2 < 32; e2++) {
        float w = Wq[(size_t)e2 * M_ + tid];
        #pragma unroll
        for (int d = 0; d < 32; d++) acc3[d] = fmaf(w, ktv[e2][d], acc3[d]);
    }
    const float scale = 0.17677669529663687f;
    float* ETs = ET + (size_t)slab * MM_;
    #pragma unroll
    for (int d = 0; d < 32; d++)
        ETs[(size_t)(h * 32 + d) * M_ + tid] = scale * acc3[d];
}

// ============================================================
// 128x128 NT fp32 GEMM, f32x2, double-buffered (s2 only).
// ============================================================
__global__ void __launch_bounds__(256) gemm128(
    const float* __restrict__ Ab, int lda, long aStride,
    const float* __restrict__ Bb, int ldb, long bStride,
    float* __restrict__ Cb, int ldc, long cStride,
    int K, int Rlim,
    const float* __restrict__ e1,
    const float* __restrict__ e2, long e2Stride)
{
    int slab = blockIdx.z;
    const float* A = Ab + (size_t)slab * aStride;
    const float* B = Bb + (size_t)slab * bStride;
    float*       C = Cb + (size_t)slab * cStride;
    const float* E2 = e2 + (size_t)slab * e2Stride;

    int rowBase = blockIdx.x * 128;
    int colBase = blockIdx.y * 128;

    __shared__ float As[2][16][128], Bs[2][16][128];
    int tid = threadIdx.x;
    int ldRow = tid >> 1;
    int ldK   = (tid & 1) << 3;
    int tx = tid & 15, ty = tid >> 4;
    int tx4 = tx << 2, ty4 = ty << 2;

    const float* Arow = A + (size_t)(rowBase + ldRow) * lda + ldK;
    const float* Brow = B + (size_t)(colBase + ldRow) * ldb + ldK;
    bool aValid = (rowBase + ldRow) < Rlim;

    const int NT = K >> 4;

    {
        float4 av0, av1;
        if (aValid) { av0 = *(const float4*)Arow; av1 = *(const float4*)(Arow + 4); }
        else        { av0 = make_float4(0.f,0.f,0.f,0.f); av1 = av0; }
        float4 bv0 = *(const float4*)Brow;
        float4 bv1 = *(const float4*)(Brow + 4);
        As[0][ldK+0][ldRow]=av0.x; As[0][ldK+1][ldRow]=av0.y;
        As[0][ldK+2][ldRow]=av0.z; As[0][ldK+3][ldRow]=av0.w;
        As[0][ldK+4][ldRow]=av1.x; As[0][ldK+5][ldRow]=av1.y;
        As[0][ldK+6][ldRow]=av1.z; As[0][ldK+7][ldRow]=av1.w;
        Bs[0][ldK+0][ldRow]=bv0.x; Bs[0][ldK+1][ldRow]=bv0.y;
        Bs[0][ldK+2][ldRow]=bv0.z; Bs[0][ldK+3][ldRow]=bv0.w;
        Bs[0][ldK+4][ldRow]=bv1.x; Bs[0][ldK+5][ldRow]=bv1.y;
        Bs[0][ldK+6][ldRow]=bv1.z; Bs[0][ldK+7][ldRow]=bv1.w;
    }
    __syncthreads();

    u64 acc[8][4] = {};
    for (int it = 0; it < NT; it++) {
        int cur = it & 1;
        bool more = (it + 1 < NT);
        float4 nav0, nav1, nbv0, nbv1;
        if (more) {
            int k0 = (it + 1) << 4;
            if (aValid) { nav0 = *(const float4*)(Arow + k0); nav1 = *(const float4*)(Arow + k0 + 4); }
            else        { nav0 = make_float4(0.f,0.f,0.f,0.f); nav1 = nav0; }
            nbv0 = *(const float4*)(Brow + k0);
            nbv1 = *(const float4*)(Brow + k0 + 4);
        }

        #pragma unroll
        for (int k = 0; k < 16; k++) {
            float4 a0 = *(const float4*)&As[cur][k][ty4];
            float4 a1 = *(const float4*)&As[cur][k][ty4 + 64];
            ulonglong2 b0 = *(const ulonglong2*)&Bs[cur][k][tx4];
            ulonglong2 b1 = *(const ulonglong2*)&Bs[cur][k][tx4 + 64];
            u64 a2;
            a2 = dup2(a0.x); fma2(acc[0][0],a2,b0.x); fma2(acc[0][1],a2,b0.y); fma2(acc[0][2],a2,b1.x); fma2(acc[0][3],a2,b1.y);
            a2 = dup2(a0.y); fma2(acc[1][0],a2,b0.x); fma2(acc[1][1],a2,b0.y); fma2(acc[1][2],a2,b1.x); fma2(acc[1][3],a2,b1.y);
            a2 = dup2(a0.z); fma2(acc[2][0],a2,b0.x); fma2(acc[2][1],a2,b0.y); fma2(acc[2][2],a2,b1.x); fma2(acc[2][3],a2,b1.y);
            a2 = dup2(a0.w); fma2(acc[3][0],a2,b0.x); fma2(acc[3][1],a2,b0.y); fma2(acc[3][2],a2,b1.x); fma2(acc[3][3],a2,b1.y);
            a2 = dup2(a1.x); fma2(acc[4][0],a2,b0.x); fma2(acc[4][1],a2,b0.y); fma2(acc[4][2],a2,b1.x); fma2(acc[4][3],a2,b1.y);
            a2 = dup2(a1.y); fma2(acc[5][0],a2,b0.x); fma2(acc[5][1],a2,b0.y); fma2(acc[5][2],a2,b1.x); fma2(acc[5][3],a2,b1.y);
            a2 = dup2(a1.z); fma2(acc[6][0],a2,b0.x); fma2(acc[6][1],a2,b0.y); fma2(acc[6][2],a2,b1.x); fma2(acc[6][3],a2,b1.y);
            a2 = dup2(a1.w); fma2(acc[7][0],a2,b0.x); fma2(acc[7][1],a2,b0.y); fma2(acc[7][2],a2,b1.x); fma2(acc[7][3],a2,b1.y);
        }

        if (more) {
            int nxt = cur ^ 1;
            As[nxt][ldK+0][ldRow]=nav0.x; As[nxt][ldK+1][ldRow]=nav0.y;
            As[nxt][ldK+2][ldRow]=nav0.z; As[nxt][ldK+3][ldRow]=nav0.w;
            As[nxt][ldK+4][ldRow]=nav1.x; As[nxt][ldK+5][ldRow]=nav1.y;
            As[nxt][ldK+6][ldRow]=nav1.z; As[nxt][ldK+7][ldRow]=nav1.w;
            Bs[nxt][ldK+0][ldRow]=nbv0.x; Bs[nxt][ldK+1][ldRow]=nbv0.y;
            Bs[nxt][ldK+2][ldRow]=nbv0.z; Bs[nxt][ldK+3][ldRow]=nbv0.w;
            Bs[nxt][ldK+4][ldRow]=nbv1.x; Bs[nxt][ldK+5][ldRow]=nbv1.y;
            Bs[nxt][ldK+6][ldRow]=nbv1.z; Bs[nxt][ldK+7][ldRow]=nbv1.w;
        }
        __syncthreads();
    }

    #pragma unroll
    for (int i = 0; i < 8; i++) {
        int r = rowBase + ty4 + (i & 3) + ((i >> 2) << 6);
        if (r >= Rlim) continue;
        #pragma unroll
        for (int j2 = 0; j2 < 4; j2++) {
            int c = colBase + tx4 + ((j2 & 1) << 1) + ((j2 >> 1) << 6);
            float2 v = unpack2(acc[i][j2]);
            size_t idx = (size_t)r * ldc + c;
            v.x = v.x * e1[c]     + E2[idx];
            v.y = v.y * e1[c + 1] + E2[idx + 1];
            *(float2*)(C + idx) = v;
        }
    }
}

// ============================================================
// 3xTF32 tensor-core NT GEMM; fp32 in GMEM, hi/lo split done
// ONCE at the smem-store stage (uint2 tiles in smem).
// 128x128 CTA, 8 warps (2x4), 64x32 per warp, m16n8k8.
//   mode 1: C = gelu(acc + bias[c])
//   mode 2: C = acc + bias[c] + resid[r,c]
// ============================================================
#define SU 20   // smem row stride in uint2; SU%16==4 -> conflict-free LDS.64
__device__ __forceinline__ void store_split8(uint2* p, float4 f0, float4 f1)
{
    uint2 s0 = split_tf32(f0.x), s1 = split_tf32(f0.y);
    uint2 s2 = split_tf32(f0.z), s3 = split_tf32(f0.w);
    *(uint4*)(p + 0) = make_uint4(s0.x, s0.y, s1.x, s1.y);
    *(uint4*)(p + 2) = make_uint4(s2.x, s2.y, s3.x, s3.y);
    s0 = split_tf32(f1.x); s1 = split_tf32(f1.y);
    s2 = split_tf32(f1.z); s3 = split_tf32(f1.w);
    *(uint4*)(p + 4) = make_uint4(s0.x, s0.y, s1.x, s1.y);
    *(uint4*)(p + 6) = make_uint4(s2.x, s2.y, s3.x, s3.y);
}

__global__ void __launch_bounds__(256) tf32_gemm(
    const float* __restrict__ A, int lda,
    const float* __restrict__ B, int ldb,
    float* __restrict__ C, int ldc,
    int K, int Rlim, int mode,
    const float* __restrict__ bias,
    const float* __restrict__ resid)
{
    extern __shared__ __align__(16) uint2 dsm[];
    uint2* AsBuf[2] = { dsm,               dsm + 128 * SU };
    uint2* BsBuf[2] = { dsm + 2 * 128 * SU, dsm + 3 * 128 * SU };

    int tid = threadIdx.x;
    int rowBase = blockIdx.x * 128, colBase = blockIdx.y * 128;

    int ldRow = tid >> 1;            // 0..127
    int ldK   = (tid & 1) << 3;      // 0 or 8
    const float* Arow = A + (size_t)(rowBase + ldRow) * lda + ldK;
    const float* Brow = B + (size_t)(colBase + ldRow) * ldb + ldK;
    bool aValid = (rowBase + ldRow) < Rlim;

    int lane = tid & 31, warp = tid >> 5;
    int wRow = (warp >> 2) << 6;     // 0 or 64
    int wCol = (warp & 3) << 5;      // 0,32,64,96
    int g = lane >> 2, t = lane & 3;

    const int NT = K >> 4;
    const float4 z4 = make_float4(0.f, 0.f, 0.f, 0.f);

    // preload tile 0
    {
        float4 a0 = aValid ? *(const float4*)Arow : z4;
        float4 a1 = aValid ? *(const float4*)(Arow + 4) : z4;
        store_split8(AsBuf[0] + ldRow * SU + ldK, a0, a1);
        float4 b0 = *(const float4*)Brow;
        float4 b1 = *(const float4*)(Brow + 4);
        store_split8(BsBuf[0] + ldRow * SU + ldK, b0, b1);
    }
    __syncthreads();

    float acc[4][4][4];
    #pragma unroll
    for (int i = 0; i < 4; i++)
        #pragma unroll
        for (int j = 0; j < 4; j++)
            #pragma unroll
            for (int q = 0; q < 4; q++) acc[i][j][q] = 0.f;

    for (int it = 0; it < NT; it++) {
        int cur = it & 1;
        bool more = (it + 1 < NT);
        float4 na0, na1, nb0, nb1;
        if (more) {
            int k0 = (it + 1) << 4;
            na0 = aValid ? *(const float4*)(Arow + k0) : z4;
            na1 = aValid ? *(const float4*)(Arow + k0 + 4) : z4;
            nb0 = *(const float4*)(Brow + k0);
            nb1 = *(const float4*)(Brow + k0 + 4);
        }

        const uint2* sa = AsBuf[cur];
        const uint2* sb = BsBuf[cur];
        #pragma unroll
        for (int ks = 0; ks < 2; ks++) {
            int kk = (ks << 3) + t;
            uint2 af[4][4];
            #pragma unroll
            for (int mb = 0; mb < 4; mb++) {
                int rb = wRow + (mb << 4);
                af[mb][0] = sa[(rb + g)     * SU + kk];
                af[mb][1] = sa[(rb + g + 8) * SU + kk];
                af[mb][2] = sa[(rb + g)     * SU + kk + 4];
                af[mb][3] = sa[(rb + g + 8) * SU + kk + 4];
            }
            uint2 bf[4][2];
            #pragma unroll
            for (int nb = 0; nb < 4; nb++) {
                int cb = wCol + (nb << 3);
                bf[nb][0] = sb[(cb + g) * SU + kk];
                bf[nb][1] = sb[(cb + g) * SU + kk + 4];
            }
            // ah*bl
            #pragma unroll
            for (int mb = 0; mb < 4; mb++)
                #pragma unroll
                for (int nb = 0; nb < 4; nb++)
                    mma_tf32(acc[mb][nb], af[mb][0].x, af[mb][1].x, af[mb][2].x, af[mb][3].x,
                             bf[nb][0].y, bf[nb][1].y);
            // al*bh
            #pragma unroll
            for (int mb = 0; mb < 4; mb++)
                #pragma unroll
                for (int nb = 0; nb < 4; nb++)
                    mma_tf32(acc[mb][nb], af[mb][0].y, af[mb][1].y, af[mb][2].y, af[mb][3].y,
                             bf[nb][0].x, bf[nb][1].x);
            // ah*bh
            #pragma unroll
            for (int mb = 0; mb < 4; mb++)
                #pragma unroll
                for (int nb = 0; nb < 4; nb++)
                    mma_tf32(acc[mb][nb], af[mb][0].x, af[mb][1].x, af[mb][2].x, af[mb][3].x,
                             bf[nb][0].x, bf[nb][1].x);
        }

        if (more) {
            int nxt = cur ^ 1;
            store_split8(AsBuf[nxt] + ldRow * SU + ldK, na0, na1);
            store_split8(BsBuf[nxt] + ldRow * SU + ldK, nb0, nb1);
        }
        __syncthreads();
    }

    // epilogue
    const float inv_sqrt2 = 0.7071067811865475f;
    #pragma unroll
    for (int mb = 0; mb < 4; mb++) {
        int r0 = rowBase + wRow + (mb << 4) + g;
        #pragma unroll
        for (int half = 0; half < 2; half++) {
            int r = r0 + half * 8;
            if (r >= Rlim) continue;
            #pragma unroll
            for (int nb = 0; nb < 4; nb++) {
                int c = colBase + wCol + (nb << 3) + (t << 1);
                float vx = acc[mb][nb][half * 2 + 0];
                float vy = acc[mb][nb][half * 2 + 1];
                if (mode == 1) {
                    vx += bias[c];
                    vy += bias[c + 1];
                    vx = 0.5f * vx * (1.0f + erff(vx * inv_sqrt2));
                    vy = 0.5f * vy * (1.0f + erff(vy * inv_sqrt2));
                } else {
                    const float* rr = resid + (size_t)r * ldc + c;
                    vx += bias[c]     + rr[0];
                    vy += bias[c + 1] + rr[1];
                }
                *(float2*)(C + (size_t)r * ldc + c) = make_float2(vx, vy);
            }
        }
    }
}

// ============================================================
// Launch
// ============================================================
extern "C" void kernel_launch(void* const* d_in, const int* in_sizes, int n_in,
                              void* d_out, int out_size)
{
    (void)in_sizes; (void)n_in; (void)out_size;
    const float* savespace = (const float*)d_in[1];
    const float* Wqkv      = (const float*)d_in[2];
    const float* Wo        = (const float*)d_in[3];
    const float* ln1_g     = (const float*)d_in[4];
    const float* ln1_b     = (const float*)d_in[5];
    const float* ln2_g     = (const float*)d_in[6];
    const float* ln2_b     = (const float*)d_in[7];
    const float* fc1_w     = (const float*)d_in[8];
    const float* fc1_b     = (const float*)d_in[9];
    const float* fc2_w     = (const float*)d_in[10];
    const float* fc2_b     = (const float*)d_in[11];
    float* out = (float*)d_out;

    float *p_sln, *p_s2, *p_hln, *p_h1, *p_G, *p_Gp, *p_T, *p_ET, *p_ws;
    cudaGetSymbolAddress((void**)&p_sln, g_sln);
    cudaGetSymbolAddress((void**)&p_s2,  g_s2);
    cudaGetSymbolAddress((void**)&p_hln, g_hln);
    cudaGetSymbolAddress((void**)&p_h1,  g_h1);
    cudaGetSymbolAddress((void**)&p_G,   g_G);
    cudaGetSymbolAddress((void**)&p_Gp,  g_Gp);
    cudaGetSymbolAddress((void**)&p_T,   g_T);
    cudaGetSymbolAddress((void**)&p_ET,  g_ET);
    cudaGetSymbolAddress((void**)&p_ws,  g_wosum);

    const long SLAB = (long)J_ * M_;
    const long MM   = MM_;
    const int TSMEM = 4 * 128 * SU * 8;   // 81920 bytes
    cudaFuncSetAttribute(tf32_gemm, cudaFuncAttributeMaxDynamicSharedMemorySize, TSMEM);

    // 1) layernorm1
    ln_kernel<<<RTOT, 256>>>(savespace, ln1_g, ln1_b, p_sln);
    // 2) Gram partials (J split in NCH chunks) + reduce
    gram_kernel<<<dim3(4, 4, NSLAB * NCH), 256>>>(p_sln, p_Gp);
    gram_reduce<<<dim3(64, NSLAB), 256>>>(p_Gp, p_G);
    // 3) Wo row sums
    rowsum_kernel<<<1, 256>>>(Wo, p_ws);
    // 4) T = G @ Wv_full^T per slab
    gemm64<<<dim3(4, 4, NSLAB), 256>>>(
        p_G, M_, MM,  Wqkv + 2 * H_ * DH_ * M_, M_, 0,  p_T, M_, MM, M_);
    // 5) finish ET per (head, slab)
    assemble2_kernel<<<dim3(H_, NSLAB), 256>>>(Wqkv, p_T, p_ET);
    // 6) s2 = wosum * (s_ln @ E) + savespace
    gemm128<<<dim3(9, 2, NSLAB), 256>>>(
        p_sln, M_, SLAB,  p_ET, M_, MM,  p_s2, M_, SLAB,
        M_, J_, p_ws, savespace, SLAB);
    // 7) layernorm2
    ln_kernel<<<RTOT, 256>>>(p_s2, ln2_g, ln2_b, p_hln);
    // 8) h1 = gelu(hln @ fc1_w^T + b1)   [smem-split 3xTF32]
    tf32_gemm<<<dim3(129, 8), 256, TSMEM>>>(
        p_hln, M_, fc1_w, M_, p_h1, FF_,
        M_, RTOT, 1, fc1_b, (const float*)0);
    // 9) out = h1 @ fc2_w^T + b2 + s2    [smem-split 3xTF32]
    tf32_gemm<<<dim3(129, 2), 256, TSMEM>>>(
        p_h1, FF_, fc2_w, FF_, out, M_,
        FF_, RTOT, 2, fc2_b, p_s2);
}

// round 9
// speedup vs baseline: 1.6306x; 1.4144x over previous
#include <cuda_runtime.h>
#include <math.h>
#include <cstdint>

// Shapes (fixed by the problem)
#define B_    2
#define I_    8
#define J_    1025
#define M_    256
#define H_    8
#define DH_   32
#define NSLAB 16              // B_*I_
#define RTOT  (NSLAB * J_)    // 16400
#define FF_   1024            // 4*M
#define NCH   5               // gram J-chunks
#define MM_   (M_ * M_)

typedef unsigned long long u64;

// ---- scratch (static __device__ arrays; no runtime allocation) ----
__device__ float g_sln[RTOT * M_];
__device__ float g_s2 [RTOT * M_];
__device__ float g_hln[RTOT * M_];
__device__ float g_h1 [(size_t)RTOT * FF_];
__device__ float g_G  [NSLAB * MM_];
__device__ float g_Gp [NCH * NSLAB * MM_];     // gram partials
__device__ float g_T  [NSLAB * MM_];
__device__ float g_ET [NSLAB * MM_];
__device__ float g_wosum[M_];

// ---- f32x2 packed-FMA helpers ----
__device__ __forceinline__ u64 dup2(float x) {
    u64 r; asm("mov.b64 %0, {%1,%1};" : "=l"(r) : "f"(x)); return r;
}
__device__ __forceinline__ void fma2(u64& d, u64 a, u64 b) {
    asm("fma.rn.f32x2 %0, %1, %2, %0;" : "+l"(d) : "l"(a), "l"(b));
}
__device__ __forceinline__ float2 unpack2(u64 v) {
    float2 r; asm("mov.b64 {%0,%1}, %2;" : "=f"(r.x), "=f"(r.y) : "l"(v)); return r;
}

// ---- tf32 mma helpers ----
__device__ __forceinline__ uint32_t f2tf32(float x) {
    uint32_t r; asm("cvt.rna.tf32.f32 %0, %1;" : "=r"(r) : "f"(x)); return r;
}
__device__ __forceinline__ void mma_tf32(float* c,
    uint32_t a0, uint32_t a1, uint32_t a2, uint32_t a3,
    uint32_t b0, uint32_t b1)
{
    asm("mma.sync.aligned.m16n8k8.row.col.f32.tf32.tf32.f32 "
        "{%0,%1,%2,%3}, {%4,%5,%6,%7}, {%8,%9}, {%0,%1,%2,%3};"
        : "+f"(c[0]), "+f"(c[1]), "+f"(c[2]), "+f"(c[3])
        : "r"(a0), "r"(a1), "r"(a2), "r"(a3), "r"(b0), "r"(b1));
}

// ============================================================
// LayerNorm over last dim M_=256, one block (256 thr) per row
// ============================================================
__global__ void ln_kernel(const float* __restrict__ x,
                          const float* __restrict__ g,
                          const float* __restrict__ b,
                          float* __restrict__ out)
{
    int row = blockIdx.x;
    const float* xr = x + (size_t)row * M_;
    int t = threadIdx.x;
    float v = xr[t];

    __shared__ float sm[8];
    float s = v;
    #pragma unroll
    for (int o = 16; o > 0; o >>= 1) s += __shfl_xor_sync(0xffffffffu, s, o);
    if ((t & 31) == 0) sm[t >> 5] = s;
    __syncthreads();
    float mean = 0.f;
    #pragma unroll
    for (int i = 0; i < 8; i++) mean += sm[i];
    mean *= (1.0f / M_);
    __syncthreads();
    float d = v - mean;
    float q = d * d;
    #pragma unroll
    for (int o = 16; o > 0; o >>= 1) q += __shfl_xor_sync(0xffffffffu, q, o);
    if ((t & 31) == 0) sm[t >> 5] = q;
    __syncthreads();
    float var = 0.f;
    #pragma unroll
    for (int i = 0; i < 8; i++) var += sm[i];
    var *= (1.0f / M_);

    out[(size_t)row * M_ + t] = d * rsqrtf(var + 1e-5f) * g[t] + b[t];
}

// ============================================================
// Wo row sums — one warp per row, coalesced, 32 blocks
// ============================================================
__global__ void rowsum_kernel(const float* __restrict__ Wo, float* __restrict__ ws)
{
    int warp = threadIdx.x >> 5, lane = threadIdx.x & 31;
    int n = blockIdx.x * 8 + warp;           // 32 blocks * 8 warps = 256 rows
    const float* row = Wo + (size_t)n * M_;
    float s = 0.f;
    #pragma unroll
    for (int m = lane; m < M_; m += 32) s += row[m];
    #pragma unroll
    for (int o = 16; o > 0; o >>= 1) s += __shfl_xor_sync(0xffffffffu, s, o);
    if (lane == 0) ws[n] = s;
}

// ============================================================
// Gram partials: Gp[slab,ch] = S_chunk^T S_chunk, J split in NCH
// chunks of 13 16-row tiles each. Symmetric blocks mirrored.
// ============================================================
__global__ void __launch_bounds__(256) gram_kernel(const float* __restrict__ sln,
                                                   float* __restrict__ Gp)
{
    if (blockIdx.y < blockIdx.x) return;
    int zc = blockIdx.z;
    int slab = zc / NCH;
    int ch = zc - slab * NCH;
    const float* A = sln + (size_t)slab * J_ * M_;
    int p0 = blockIdx.x * 64, q0 = blockIdx.y * 64;

    int t0 = ch * 13, t1 = t0 + 13;   // 65 tiles total = 5*13

    __shared__ float As[2][16][64], Bs[2][16][64];
    int tid = threadIdx.x;
    int jj = tid >> 4;
    int cq = (tid & 15) << 2;
    int tx = tid & 15, ty = tid >> 4;

    float4 av, bv;
    {
        int j = t0 * 16 + jj;
        if (j < J_) {
            av = *(const float4*)(A + (size_t)j * M_ + p0 + cq);
            bv = *(const float4*)(A + (size_t)j * M_ + q0 + cq);
        } else { av = make_float4(0.f,0.f,0.f,0.f); bv = av; }
    }
    *(float4*)&As[0][jj][cq] = av;
    *(float4*)&Bs[0][jj][cq] = bv;
    __syncthreads();

    u64 acc[4][2] = {};
    for (int it = t0; it < t1; it++) {
        int cur = (it - t0) & 1;
        float4 nav, nbv;
        bool more = (it + 1 < t1);
        if (more) {
            int j = (it + 1) * 16 + jj;
            if (j < J_) {
                nav = *(const float4*)(A + (size_t)j * M_ + p0 + cq);
                nbv = *(const float4*)(A + (size_t)j * M_ + q0 + cq);
            } else { nav = make_float4(0.f,0.f,0.f,0.f); nbv = nav; }
        }
        #pragma unroll
        for (int k = 0; k < 16; k++) {
            float4 a = *(const float4*)&As[cur][k][ty << 2];
            ulonglong2 b = *(const ulonglong2*)&Bs[cur][k][tx << 2];
            u64 a2;
            a2 = dup2(a.x); fma2(acc[0][0], a2, b.x); fma2(acc[0][1], a2, b.y);
            a2 = dup2(a.y); fma2(acc[1][0], a2, b.x); fma2(acc[1][1], a2, b.y);
            a2 = dup2(a.z); fma2(acc[2][0], a2, b.x); fma2(acc[2][1], a2, b.y);
            a2 = dup2(a.w); fma2(acc[3][0], a2, b.x); fma2(acc[3][1], a2, b.y);
        }
        if (more) {
            *(float4*)&As[cur ^ 1][jj][cq] = nav;
            *(float4*)&Bs[cur ^ 1][jj][cq] = nbv;
        }
        __syncthreads();
    }
    float* Gs = Gp + (size_t)zc * MM_;
    #pragma unroll
    for (int i = 0; i < 4; i++) {
        int p = p0 + (ty << 2) + i;
        #pragma unroll
        for (int j2 = 0; j2 < 2; j2++) {
            float2 v = unpack2(acc[i][j2]);
            int q = q0 + (tx << 2) + j2 * 2;
            Gs[(size_t)p * M_ + q]     = v.x;
            Gs[(size_t)p * M_ + q + 1] = v.y;
            Gs[(size_t)q * M_ + p]       = v.x;
            Gs[(size_t)(q + 1) * M_ + p] = v.y;
        }
    }
}

// ============================================================
// Gram reduce: G[slab] = sum_ch Gp[slab,ch]
// ============================================================
__global__ void gram_reduce(const float* __restrict__ Gp, float* __restrict__ G)
{
    int slab = blockIdx.y;
    int idx = (blockIdx.x * 256 + threadIdx.x) * 4;
    const float* base = Gp + (size_t)slab * NCH * MM_ + idx;
    float4 s = *(const float4*)base;
    #pragma unroll
    for (int ch = 1; ch < NCH; ch++) {
        float4 v = *(const float4*)(base + (size_t)ch * MM_);
        s.x += v.x; s.y += v.y; s.z += v.z; s.w += v.w;
    }
    *(float4*)(G + (size_t)slab * MM_ + idx) = s;
}

// ============================================================
// 64x64 NT GEMM (T = G @ Wv^T)
// ============================================================
__global__ void __launch_bounds__(256) gemm64(
    const float* __restrict__ Ab, int lda, long aStride,
    const float* __restrict__ Bb, int ldb, long bStride,
    float* __restrict__ Cb, int ldc, long cStride, int K)
{
    int slab = blockIdx.z;
    const float* A = Ab + (size_t)slab * aStride;
    const float* B = Bb + (size_t)slab * bStride;
    float*       C = Cb + (size_t)slab * cStride;

    int rowBase = blockIdx.x * 64;
    int colBase = blockIdx.y * 64;

    __shared__ float As[16][64], Bs[16][64];
    int tid = threadIdx.x;
    int lm = tid >> 2;
    int lk = (tid & 3) << 2;
    int tx = tid & 15, ty = tid >> 4;

    u64 acc[4][2] = {};
    for (int k0 = 0; k0 < K; k0 += 16) {
        float4 av = *(const float4*)(A + (size_t)(rowBase + lm) * lda + k0 + lk);
        As[lk + 0][lm] = av.x; As[lk + 1][lm] = av.y;
        As[lk + 2][lm] = av.z; As[lk + 3][lm] = av.w;
        float4 bv = *(const float4*)(B + (size_t)(colBase + lm) * ldb + k0 + lk);
        Bs[lk + 0][lm] = bv.x; Bs[lk + 1][lm] = bv.y;
        Bs[lk + 2][lm] = bv.z; Bs[lk + 3][lm] = bv.w;
        __syncthreads();
        #pragma unroll
        for (int k = 0; k < 16; k++) {
            float4 a = *(const float4*)&As[k][ty << 2];
            ulonglong2 b = *(const ulonglong2*)&Bs[k][tx << 2];
            u64 a2;
            a2 = dup2(a.x); fma2(acc[0][0], a2, b.x); fma2(acc[0][1], a2, b.y);
            a2 = dup2(a.y); fma2(acc[1][0], a2, b.x); fma2(acc[1][1], a2, b.y);
            a2 = dup2(a.z); fma2(acc[2][0], a2, b.x); fma2(acc[2][1], a2, b.y);
            a2 = dup2(a.w); fma2(acc[3][0], a2, b.x); fma2(acc[3][1], a2, b.y);
        }
        __syncthreads();
    }
    #pragma unroll
    for (int i = 0; i < 4; i++) {
        int r = rowBase + (ty << 2) + i;
        #pragma unroll
        for (int j2 = 0; j2 < 2; j2++) {
            int c = colBase + (tx << 2) + j2 * 2;
            float2 v = unpack2(acc[i][j2]);
            *(float2*)(C + (size_t)r * ldc + c) = v;
        }
    }
}

// ============================================================
// Small per-(head,slab) finisher
// ============================================================
__global__ void __launch_bounds__(256) assemble2_kernel(const float* __restrict__ Wqkv,
                                                        const float* __restrict__ T,
                                                        float* __restrict__ ET)
{
    int h = blockIdx.x;
    int slab = blockIdx.y;
    const float* Ts = T + (size_t)slab * MM_;
    const float* Wq = Wqkv + (size_t)(0 * H_ + h) * DH_ * M_;
    const float* Wk = Wqkv + (size_t)(1 * H_ + h) * DH_ * M_;

    __shared__ float sT[256][33];
    __shared__ float ktv[32][33];
    int tid = threadIdx.x;

    {
        int m = tid >> 5, d = tid & 31;
        #pragma unroll
        for (int pass = 0; pass < 32; pass++) {
            int mm = pass * 8 + m;
            sT[mm][d] = Ts[(size_t)mm * M_ + h * 32 + d];
        }
    }
    __syncthreads();

    {
        int d  = tid & 31;
        int e0 = (tid >> 5) << 2;
        float acc4[4] = {0.f, 0.f, 0.f, 0.f};
        for (int m = 0; m < 256; m++) {
            float t = sT[m][d];
            #pragma unroll
            for (int ee = 0; ee < 4; ee++)
                acc4[ee] = fmaf(Wk[(size_t)(e0 + ee) * M_ + m], t, acc4[ee]);
        }
        #pragma unroll
        for (int ee = 0; ee < 4; ee++)
            ktv[e0 + ee][d] = acc4[ee];
    }
    __syncthreads();

    float acc3[32];
    #pragma unroll
    for (int d = 0; d < 32; d++) acc3[d] = 0.f;
    for (int e2 = 0; e2 < 32; e2++) {
        float w = Wq[(size_t)e2 * M_ + tid];
        #pragma unroll
        for (int d = 0; d < 32; d++) acc3[d] = fmaf(w, ktv[e2][d], acc3[d]);
    }
    const float scale = 0.17677669529663687f;
    float* ETs = ET + (size_t)slab * MM_;
    #pragma unroll
    for (int d = 0; d < 32; d++)
        ETs[(size_t)(h * 32 + d) * M_ + tid] = scale * acc3[d];
}

// ============================================================
// 128x128 NT fp32 GEMM, f32x2, double-buffered (s2 only).
// ============================================================
__global__ void __launch_bounds__(256) gemm128(
    const float* __restrict__ Ab, int lda, long aStride,
    const float* __restrict__ Bb, int ldb, long bStride,
    float* __restrict__ Cb, int ldc, long cStride,
    int K, int Rlim,
    const float* __restrict__ e1,
    const float* __restrict__ e2, long e2Stride)
{
    int slab = blockIdx.z;
    const float* A = Ab + (size_t)slab * aStride;
    const float* B = Bb + (size_t)slab * bStride;
    float*       C = Cb + (size_t)slab * cStride;
    const float* E2 = e2 + (size_t)slab * e2Stride;

    int rowBase = blockIdx.x * 128;
    int colBase = blockIdx.y * 128;

    __shared__ float As[2][16][128], Bs[2][16][128];
    int tid = threadIdx.x;
    int ldRow = tid >> 1;
    int ldK   = (tid & 1) << 3;
    int tx = tid & 15, ty = tid >> 4;
    int tx4 = tx << 2, ty4 = ty << 2;

    const float* Arow = A + (size_t)(rowBase + ldRow) * lda + ldK;
    const float* Brow = B + (size_t)(colBase + ldRow) * ldb + ldK;
    bool aValid = (rowBase + ldRow) < Rlim;

    const int NT = K >> 4;

    {
        float4 av0, av1;
        if (aValid) { av0 = *(const float4*)Arow; av1 = *(const float4*)(Arow + 4); }
        else        { av0 = make_float4(0.f,0.f,0.f,0.f); av1 = av0; }
        float4 bv0 = *(const float4*)Brow;
        float4 bv1 = *(const float4*)(Brow + 4);
        As[0][ldK+0][ldRow]=av0.x; As[0][ldK+1][ldRow]=av0.y;
        As[0][ldK+2][ldRow]=av0.z; As[0][ldK+3][ldRow]=av0.w;
        As[0][ldK+4][ldRow]=av1.x; As[0][ldK+5][ldRow]=av1.y;
        As[0][ldK+6][ldRow]=av1.z; As[0][ldK+7][ldRow]=av1.w;
        Bs[0][ldK+0][ldRow]=bv0.x; Bs[0][ldK+1][ldRow]=bv0.y;
        Bs[0][ldK+2][ldRow]=bv0.z; Bs[0][ldK+3][ldRow]=bv0.w;
        Bs[0][ldK+4][ldRow]=bv1.x; Bs[0][ldK+5][ldRow]=bv1.y;
        Bs[0][ldK+6][ldRow]=bv1.z; Bs[0][ldK+7][ldRow]=bv1.w;
    }
    __syncthreads();

    u64 acc[8][4] = {};
    for (int it = 0; it < NT; it++) {
        int cur = it & 1;
        bool more = (it + 1 < NT);
        float4 nav0, nav1, nbv0, nbv1;
        if (more) {
            int k0 = (it + 1) << 4;
            if (aValid) { nav0 = *(const float4*)(Arow + k0); nav1 = *(const float4*)(Arow + k0 + 4); }
            else        { nav0 = make_float4(0.f,0.f,0.f,0.f); nav1 = nav0; }
            nbv0 = *(const float4*)(Brow + k0);
            nbv1 = *(const float4*)(Brow + k0 + 4);
        }

        #pragma unroll
        for (int k = 0; k < 16; k++) {
            float4 a0 = *(const float4*)&As[cur][k][ty4];
            float4 a1 = *(const float4*)&As[cur][k][ty4 + 64];
            ulonglong2 b0 = *(const ulonglong2*)&Bs[cur][k][tx4];
            ulonglong2 b1 = *(const ulonglong2*)&Bs[cur][k][tx4 + 64];
            u64 a2;
            a2 = dup2(a0.x); fma2(acc[0][0],a2,b0.x); fma2(acc[0][1],a2,b0.y); fma2(acc[0][2],a2,b1.x); fma2(acc[0][3],a2,b1.y);
            a2 = dup2(a0.y); fma2(acc[1][0],a2,b0.x); fma2(acc[1][1],a2,b0.y); fma2(acc[1][2],a2,b1.x); fma2(acc[1][3],a2,b1.y);
            a2 = dup2(a0.z); fma2(acc[2][0],a2,b0.x); fma2(acc[2][1],a2,b0.y); fma2(acc[2][2],a2,b1.x); fma2(acc[2][3],a2,b1.y);
            a2 = dup2(a0.w); fma2(acc[3][0],a2,b0.x); fma2(acc[3][1],a2,b0.y); fma2(acc[3][2],a2,b1.x); fma2(acc[3][3],a2,b1.y);
            a2 = dup2(a1.x); fma2(acc[4][0],a2,b0.x); fma2(acc[4][1],a2,b0.y); fma2(acc[4][2],a2,b1.x); fma2(acc[4][3],a2,b1.y);
            a2 = dup2(a1.y); fma2(acc[5][0],a2,b0.x); fma2(acc[5][1],a2,b0.y); fma2(acc[5][2],a2,b1.x); fma2(acc[5][3],a2,b1.y);
            a2 = dup2(a1.z); fma2(acc[6][0],a2,b0.x); fma2(acc[6][1],a2,b0.y); fma2(acc[6][2],a2,b1.x); fma2(acc[6][3],a2,b1.y);
            a2 = dup2(a1.w); fma2(acc[7][0],a2,b0.x); fma2(acc[7][1],a2,b0.y); fma2(acc[7][2],a2,b1.x); fma2(acc[7][3],a2,b1.y);
        }

        if (more) {
            int nxt = cur ^ 1;
            As[nxt][ldK+0][ldRow]=nav0.x; As[nxt][ldK+1][ldRow]=nav0.y;
            As[nxt][ldK+2][ldRow]=nav0.z; As[nxt][ldK+3][ldRow]=nav0.w;
            As[nxt][ldK+4][ldRow]=nav1.x; As[nxt][ldK+5][ldRow]=nav1.y;
            As[nxt][ldK+6][ldRow]=nav1.z; As[nxt][ldK+7][ldRow]=nav1.w;
            Bs[nxt][ldK+0][ldRow]=nbv0.x; Bs[nxt][ldK+1][ldRow]=nbv0.y;
            Bs[nxt][ldK+2][ldRow]=nbv0.z; Bs[nxt][ldK+3][ldRow]=nbv0.w;
            Bs[nxt][ldK+4][ldRow]=nbv1.x; Bs[nxt][ldK+5][ldRow]=nbv1.y;
            Bs[nxt][ldK+6][ldRow]=nbv1.z; Bs[nxt][ldK+7][ldRow]=nbv1.w;
        }
        __syncthreads();
    }

    #pragma unroll
    for (int i = 0; i < 8; i++) {
        int r = rowBase + ty4 + (i & 3) + ((i >> 2) << 6);
        if (r >= Rlim) continue;
        #pragma unroll
        for (int j2 = 0; j2 < 4; j2++) {
            int c = colBase + tx4 + ((j2 & 1) << 1) + ((j2 >> 1) << 6);
            float2 v = unpack2(acc[i][j2]);
            size_t idx = (size_t)r * ldc + c;
            v.x = v.x * e1[c]     + E2[idx];
            v.y = v.y * e1[c + 1] + E2[idx + 1];
            *(float2*)(C + idx) = v;
        }
    }
}

// ============================================================
// 3xTF32 tensor-core NT GEMM (R6 version — inner-loop split)
// 128x128 CTA, 8 warps (2x4), 64x32 per warp, m16n8k8.
//   mode 1: C = gelu(acc + bias[c])
//   mode 2: C = acc + bias[c] + resid[r,c]
// ============================================================
#define BKP 20   // padded smem row stride (floats)
__global__ void __launch_bounds__(256) tf32_gemm(
    const float* __restrict__ A, int lda,
    const float* __restrict__ B, int ldb,
    float* __restrict__ C, int ldc,
    int K, int Rlim, int mode,
    const float* __restrict__ bias,
    const float* __restrict__ resid)
{
    __shared__ float As[2][128 * BKP], Bs[2][128 * BKP];
    int tid = threadIdx.x;
    int rowBase = blockIdx.x * 128, colBase = blockIdx.y * 128;

    int ldRow = tid >> 1;            // 0..127
    int ldK   = (tid & 1) << 3;      // 0 or 8
    const float* Arow = A + (size_t)(rowBase + ldRow) * lda + ldK;
    const float* Brow = B + (size_t)(colBase + ldRow) * ldb + ldK;
    bool aValid = (rowBase + ldRow) < Rlim;

    int lane = tid & 31, warp = tid >> 5;
    int wRow = (warp >> 2) << 6;     // 0 or 64
    int wCol = (warp & 3) << 5;      // 0,32,64,96
    int g = lane >> 2, t = lane & 3;

    const int NT = K >> 4;

    // preload tile 0
    {
        float4 av0, av1;
        if (aValid) { av0 = *(const float4*)Arow; av1 = *(const float4*)(Arow + 4); }
        else        { av0 = make_float4(0.f,0.f,0.f,0.f); av1 = av0; }
        float4 bv0 = *(const float4*)Brow;
        float4 bv1 = *(const float4*)(Brow + 4);
        float* pa = &As[0][ldRow * BKP + ldK];
        pa[0]=av0.x; pa[1]=av0.y; pa[2]=av0.z; pa[3]=av0.w;
        pa[4]=av1.x; pa[5]=av1.y; pa[6]=av1.z; pa[7]=av1.w;
        float* pb = &Bs[0][ldRow * BKP + ldK];
        pb[0]=bv0.x; pb[1]=bv0.y; pb[2]=bv0.z; pb[3]=bv0.w;
        pb[4]=bv1.x; pb[5]=bv1.y; pb[6]=bv1.z; pb[7]=bv1.w;
    }
    __syncthreads();

    float acc[4][4][4];
    #pragma unroll
    for (int i = 0; i < 4; i++)
        #pragma unroll
        for (int j = 0; j < 4; j++)
            #pragma unroll
            for (int q = 0; q < 4; q++) acc[i][j][q] = 0.f;

    for (int it = 0; it < NT; it++) {
        int cur = it & 1;
        bool more = (it + 1 < NT);
        float4 nav0, nav1, nbv0, nbv1;
        if (more) {
            int k0 = (it + 1) << 4;
            if (aValid) { nav0 = *(const float4*)(Arow + k0); nav1 = *(const float4*)(Arow + k0 + 4); }
            else        { nav0 = make_float4(0.f,0.f,0.f,0.f); nav1 = nav0; }
            nbv0 = *(const float4*)(Brow + k0);
            nbv1 = *(const float4*)(Brow + k0 + 4);
        }

        const float* sa = As[cur];
        const float* sb = Bs[cur];
        #pragma unroll
        for (int ks = 0; ks < 2; ks++) {
            int kk = (ks << 3) + t;
            uint32_t ahi[4][4], alo[4][4];
            #pragma unroll
            for (int mb = 0; mb < 4; mb++) {
                int rb = wRow + (mb << 4);
                float x0 = sa[(rb + g)     * BKP + kk];
                float x1 = sa[(rb + g + 8) * BKP + kk];
                float x2 = sa[(rb + g)     * BKP + kk + 4];
                float x3 = sa[(rb + g + 8) * BKP + kk + 4];
                ahi[mb][0] = f2tf32(x0); alo[mb][0] = __float_as_uint(x0 - __uint_as_float(ahi[mb][0]));
                ahi[mb][1] = f2tf32(x1); alo[mb][1] = __float_as_uint(x1 - __uint_as_float(ahi[mb][1]));
                ahi[mb][2] = f2tf32(x2); alo[mb][2] = __float_as_uint(x2 - __uint_as_float(ahi[mb][2]));
                ahi[mb][3] = f2tf32(x3); alo[mb][3] = __float_as_uint(x3 - __uint_as_float(ahi[mb][3]));
            }
            uint32_t bhi[4][2], blo[4][2];
            #pragma unroll
            for (int nb = 0; nb < 4; nb++) {
                int cb = wCol + (nb << 3);
                float y0 = sb[(cb + g) * BKP + kk];
                float y1 = sb[(cb + g) * BKP + kk + 4];
                bhi[nb][0] = f2tf32(y0); blo[nb][0] = __float_as_uint(y0 - __uint_as_float(bhi[nb][0]));
                bhi[nb][1] = f2tf32(y1); blo[nb][1] = __float_as_uint(y1 - __uint_as_float(bhi[nb][1]));
            }
            #pragma unroll
            for (int mb = 0; mb < 4; mb++)
                #pragma unroll
                for (int nb = 0; nb < 4; nb++)
                    mma_tf32(acc[mb][nb], ahi[mb][0], ahi[mb][1], ahi[mb][2], ahi[mb][3], blo[nb][0], blo[nb][1]);
            #pragma unroll
            for (int mb = 0; mb < 4; mb++)
                #pragma unroll
                for (int nb = 0; nb < 4; nb++)
                    mma_tf32(acc[mb][nb], alo[mb][0], alo[mb][1], alo[mb][2], alo[mb][3], bhi[nb][0], bhi[nb][1]);
            #pragma unroll
            for (int mb = 0; mb < 4; mb++)
                #pragma unroll
                for (int nb = 0; nb < 4; nb++)
                    mma_tf32(acc[mb][nb], ahi[mb][0], ahi[mb][1], ahi[mb][2], ahi[mb][3], bhi[nb][0], bhi[nb][1]);
        }

        if (more) {
            int nxt = cur ^ 1;
            float* pa = &As[nxt][ldRow * BKP + ldK];
            pa[0]=nav0.x; pa[1]=nav0.y; pa[2]=nav0.z; pa[3]=nav0.w;
            pa[4]=nav1.x; pa[5]=nav1.y; pa[6]=nav1.z; pa[7]=nav1.w;
            float* pb = &Bs[nxt][ldRow * BKP + ldK];
            pb[0]=nbv0.x; pb[1]=nbv0.y; pb[2]=nbv0.z; pb[3]=nbv0.w;
            pb[4]=nbv1.x; pb[5]=nbv1.y; pb[6]=nbv1.z; pb[7]=nbv1.w;
        }
        __syncthreads();
    }

    // epilogue
    const float inv_sqrt2 = 0.7071067811865475f;
    #pragma unroll
    for (int mb = 0; mb < 4; mb++) {
        int r0 = rowBase + wRow + (mb << 4) + g;
        #pragma unroll
        for (int half = 0; half < 2; half++) {
            int r = r0 + half * 8;
            if (r >= Rlim) continue;
            #pragma unroll
            for (int nb = 0; nb < 4; nb++) {
                int c = colBase + wCol + (nb << 3) + (t << 1);
                float vx = acc[mb][nb][half * 2 + 0];
                float vy = acc[mb][nb][half * 2 + 1];
                if (mode == 1) {
                    vx += bias[c];
                    vy += bias[c + 1];
                    vx = 0.5f * vx * (1.0f + erff(vx * inv_sqrt2));
                    vy = 0.5f * vy * (1.0f + erff(vy * inv_sqrt2));
                } else {
                    const float* rr = resid + (size_t)r * ldc + c;
                    vx += bias[c]     + rr[0];
                    vy += bias[c + 1] + rr[1];
                }
                *(float2*)(C + (size_t)r * ldc + c) = make_float2(vx, vy);
            }
        }
    }
}

// ============================================================
// Launch
// ============================================================
extern "C" void kernel_launch(void* const* d_in, const int* in_sizes, int n_in,
                              void* d_out, int out_size)
{
    (void)in_sizes; (void)n_in; (void)out_size;
    const float* savespace = (const float*)d_in[1];
    const float* Wqkv      = (const float*)d_in[2];
    const float* Wo        = (const float*)d_in[3];
    const float* ln1_g     = (const float*)d_in[4];
    const float* ln1_b     = (const float*)d_in[5];
    const float* ln2_g     = (const float*)d_in[6];
    const float* ln2_b     = (const float*)d_in[7];
    const float* fc1_w     = (const float*)d_in[8];
    const float* fc1_b     = (const float*)d_in[9];
    const float* fc2_w     = (const float*)d_in[10];
    const float* fc2_b     = (const float*)d_in[11];
    float* out = (float*)d_out;

    float *p_sln, *p_s2, *p_hln, *p_h1, *p_G, *p_Gp, *p_T, *p_ET, *p_ws;
    cudaGetSymbolAddress((void**)&p_sln, g_sln);
    cudaGetSymbolAddress((void**)&p_s2,  g_s2);
    cudaGetSymbolAddress((void**)&p_hln, g_hln);
    cudaGetSymbolAddress((void**)&p_h1,  g_h1);
    cudaGetSymbolAddress((void**)&p_G,   g_G);
    cudaGetSymbolAddress((void**)&p_Gp,  g_Gp);
    cudaGetSymbolAddress((void**)&p_T,   g_T);
    cudaGetSymbolAddress((void**)&p_ET,  g_ET);
    cudaGetSymbolAddress((void**)&p_ws,  g_wosum);

    const long SLAB = (long)J_ * M_;
    const long MM   = MM_;

    // 1) layernorm1
    ln_kernel<<<RTOT, 256>>>(savespace, ln1_g, ln1_b, p_sln);
    // 2) Gram partials (J split in NCH chunks) + reduce
    gram_kernel<<<dim3(4, 4, NSLAB * NCH), 256>>>(p_sln, p_Gp);
    gram_reduce<<<dim3(64, NSLAB), 256>>>(p_Gp, p_G);
    // 3) Wo row sums (parallel)
    rowsum_kernel<<<32, 256>>>(Wo, p_ws);
    // 4) T = G @ Wv_full^T per slab
    gemm64<<<dim3(4, 4, NSLAB), 256>>>(
        p_G, M_, MM,  Wqkv + 2 * H_ * DH_ * M_, M_, 0,  p_T, M_, MM, M_);
    // 5) finish ET per (head, slab)
    assemble2_kernel<<<dim3(H_, NSLAB), 256>>>(Wqkv, p_T, p_ET);
    // 6) s2 = wosum * (s_ln @ E) + savespace
    gemm128<<<dim3(9, 2, NSLAB), 256>>>(
        p_sln, M_, SLAB,  p_ET, M_, MM,  p_s2, M_, SLAB,
        M_, J_, p_ws, savespace, SLAB);
    // 7) layernorm2
    ln_kernel<<<RTOT, 256>>>(p_s2, ln2_g, ln2_b, p_hln);
    // 8) h1 = gelu(hln @ fc1_w^T + b1)   [3xTF32]
    tf32_gemm<<<dim3(129, 8), 256>>>(
        p_hln, M_, fc1_w, M_, p_h1, FF_,
        M_, RTOT, 1, fc1_b, (const float*)0);
    // 9) out = h1 @ fc2_w^T + b2 + s2    [3xTF32]
    tf32_gemm<<<dim3(129, 2), 256>>>(
        p_h1, FF_, fc2_w, FF_, out, M_,
        FF_, RTOT, 2, fc2_b, p_s2);
}

// round 10
// speedup vs baseline: 2.1264x; 1.3040x over previous
#include <cuda_runtime.h>
#include <math.h>
#include <cstdint>

// Shapes (fixed by the problem)
#define B_    2
#define I_    8
#define J_    1025
#define M_    256
#define H_    8
#define DH_   32
#define NSLAB 16              // B_*I_
#define RTOT  (NSLAB * J_)    // 16400
#define FF_   1024            // 4*M
#define NCH   5               // gram J-chunks
#define MM_   (M_ * M_)

typedef unsigned long long u64;

// ---- scratch (static __device__ arrays; no runtime allocation) ----
__device__ float g_sln[RTOT * M_];
__device__ float g_s2 [RTOT * M_];
__device__ float g_hln[RTOT * M_];
__device__ float g_h1 [(size_t)RTOT * FF_];
__device__ float g_G  [NSLAB * MM_];
__device__ float g_Gp [NCH * NSLAB * MM_];     // gram partials
__device__ float g_T  [NSLAB * MM_];
__device__ float g_ET [NSLAB * MM_];
__device__ float g_wosum[M_];

// ---- f32x2 packed-FMA helpers ----
__device__ __forceinline__ u64 dup2(float x) {
    u64 r; asm("mov.b64 %0, {%1,%1};" : "=l"(r) : "f"(x)); return r;
}
__device__ __forceinline__ void fma2(u64& d, u64 a, u64 b) {
    asm("fma.rn.f32x2 %0, %1, %2, %0;" : "+l"(d) : "l"(a), "l"(b));
}
__device__ __forceinline__ float2 unpack2(u64 v) {
    float2 r; asm("mov.b64 {%0,%1}, %2;" : "=f"(r.x), "=f"(r.y) : "l"(v)); return r;
}

// ---- bf16 mma helper (m16n8k16, sm_80+ so legal under compute_103) ----
__device__ __forceinline__ void mma_bf16(float* c,
    uint32_t a0, uint32_t a1, uint32_t a2, uint32_t a3,
    uint32_t b0, uint32_t b1)
{
    asm("mma.sync.aligned.m16n8k16.row.col.f32.bf16.bf16.f32 "
        "{%0,%1,%2,%3}, {%4,%5,%6,%7}, {%8,%9}, {%0,%1,%2,%3};"
        : "+f"(c[0]), "+f"(c[1]), "+f"(c[2]), "+f"(c[3])
        : "r"(a0), "r"(a1), "r"(a2), "r"(a3), "r"(b0), "r"(b1));
}
// pack bf16(lo(x0)), bf16(lo(x1)) into one u32 (lo0 in low half)
__device__ __forceinline__ uint32_t pack_lo2(float lo0, float lo1) {
    uint32_t r;
    asm("cvt.rn.bf16x2.f32 %0, %1, %2;" : "=r"(r) : "f"(lo1), "f"(lo0));
    return r;
}

// ============================================================
// LayerNorm over last dim M_=256, one block (256 thr) per row
// ============================================================
__global__ void ln_kernel(const float* __restrict__ x,
                          const float* __restrict__ g,
                          const float* __restrict__ b,
                          float* __restrict__ out)
{
    int row = blockIdx.x;
    const float* xr = x + (size_t)row * M_;
    int t = threadIdx.x;
    float v = xr[t];

    __shared__ float sm[8];
    float s = v;
    #pragma unroll
    for (int o = 16; o > 0; o >>= 1) s += __shfl_xor_sync(0xffffffffu, s, o);
    if ((t & 31) == 0) sm[t >> 5] = s;
    __syncthreads();
    float mean = 0.f;
    #pragma unroll
    for (int i = 0; i < 8; i++) mean += sm[i];
    mean *= (1.0f / M_);
    __syncthreads();
    float d = v - mean;
    float q = d * d;
    #pragma unroll
    for (int o = 16; o > 0; o >>= 1) q += __shfl_xor_sync(0xffffffffu, q, o);
    if ((t & 31) == 0) sm[t >> 5] = q;
    __syncthreads();
    float var = 0.f;
    #pragma unroll
    for (int i = 0; i < 8; i++) var += sm[i];
    var *= (1.0f / M_);

    out[(size_t)row * M_ + t] = d * rsqrtf(var + 1e-5f) * g[t] + b[t];
}

// ============================================================
// Wo row sums — one warp per row
// ============================================================
__global__ void rowsum_kernel(const float* __restrict__ Wo, float* __restrict__ ws)
{
    int warp = threadIdx.x >> 5, lane = threadIdx.x & 31;
    int n = blockIdx.x * 8 + warp;
    const float* row = Wo + (size_t)n * M_;
    float s = 0.f;
    #pragma unroll
    for (int m = lane; m < M_; m += 32) s += row[m];
    #pragma unroll
    for (int o = 16; o > 0; o >>= 1) s += __shfl_xor_sync(0xffffffffu, s, o);
    if (lane == 0) ws[n] = s;
}

// ============================================================
// Gram partials: J split in NCH chunks
// ============================================================
__global__ void __launch_bounds__(256) gram_kernel(const float* __restrict__ sln,
                                                   float* __restrict__ Gp)
{
    if (blockIdx.y < blockIdx.x) return;
    int zc = blockIdx.z;
    int slab = zc / NCH;
    int ch = zc - slab * NCH;
    const float* A = sln + (size_t)slab * J_ * M_;
    int p0 = blockIdx.x * 64, q0 = blockIdx.y * 64;

    int t0 = ch * 13, t1 = t0 + 13;

    __shared__ float As[2][16][64], Bs[2][16][64];
    int tid = threadIdx.x;
    int jj = tid >> 4;
    int cq = (tid & 15) << 2;
    int tx = tid & 15, ty = tid >> 4;

    float4 av, bv;
    {
        int j = t0 * 16 + jj;
        if (j < J_) {
            av = *(const float4*)(A + (size_t)j * M_ + p0 + cq);
            bv = *(const float4*)(A + (size_t)j * M_ + q0 + cq);
        } else { av = make_float4(0.f,0.f,0.f,0.f); bv = av; }
    }
    *(float4*)&As[0][jj][cq] = av;
    *(float4*)&Bs[0][jj][cq] = bv;
    __syncthreads();

    u64 acc[4][2] = {};
    for (int it = t0; it < t1; it++) {
        int cur = (it - t0) & 1;
        float4 nav, nbv;
        bool more = (it + 1 < t1);
        if (more) {
            int j = (it + 1) * 16 + jj;
            if (j < J_) {
                nav = *(const float4*)(A + (size_t)j * M_ + p0 + cq);
                nbv = *(const float4*)(A + (size_t)j * M_ + q0 + cq);
            } else { nav = make_float4(0.f,0.f,0.f,0.f); nbv = nav; }
        }
        #pragma unroll
        for (int k = 0; k < 16; k++) {
            float4 a = *(const float4*)&As[cur][k][ty << 2];
            ulonglong2 b = *(const ulonglong2*)&Bs[cur][k][tx << 2];
            u64 a2;
            a2 = dup2(a.x); fma2(acc[0][0], a2, b.x); fma2(acc[0][1], a2, b.y);
            a2 = dup2(a.y); fma2(acc[1][0], a2, b.x); fma2(acc[1][1], a2, b.y);
            a2 = dup2(a.z); fma2(acc[2][0], a2, b.x); fma2(acc[2][1], a2, b.y);
            a2 = dup2(a.w); fma2(acc[3][0], a2, b.x); fma2(acc[3][1], a2, b.y);
        }
        if (more) {
            *(float4*)&As[cur ^ 1][jj][cq] = nav;
            *(float4*)&Bs[cur ^ 1][jj][cq] = nbv;
        }
        __syncthreads();
    }
    float* Gs = Gp + (size_t)zc * MM_;
    #pragma unroll
    for (int i = 0; i < 4; i++) {
        int p = p0 + (ty << 2) + i;
        #pragma unroll
        for (int j2 = 0; j2 < 2; j2++) {
            float2 v = unpack2(acc[i][j2]);
            int q = q0 + (tx << 2) + j2 * 2;
            Gs[(size_t)p * M_ + q]     = v.x;
            Gs[(size_t)p * M_ + q + 1] = v.y;
            Gs[(size_t)q * M_ + p]       = v.x;
            Gs[(size_t)(q + 1) * M_ + p] = v.y;
        }
    }
}

// ============================================================
// Gram reduce
// ============================================================
__global__ void gram_reduce(const float* __restrict__ Gp, float* __restrict__ G)
{
    int slab = blockIdx.y;
    int idx = (blockIdx.x * 256 + threadIdx.x) * 4;
    const float* base = Gp + (size_t)slab * NCH * MM_ + idx;
    float4 s = *(const float4*)base;
    #pragma unroll
    for (int ch = 1; ch < NCH; ch++) {
        float4 v = *(const float4*)(base + (size_t)ch * MM_);
        s.x += v.x; s.y += v.y; s.z += v.z; s.w += v.w;
    }
    *(float4*)(G + (size_t)slab * MM_ + idx) = s;
}

// ============================================================
// 64x64 NT GEMM (T = G @ Wv^T)
// ============================================================
__global__ void __launch_bounds__(256) gemm64(
    const float* __restrict__ Ab, int lda, long aStride,
    const float* __restrict__ Bb, int ldb, long bStride,
    float* __restrict__ Cb, int ldc, long cStride, int K)
{
    int slab = blockIdx.z;
    const float* A = Ab + (size_t)slab * aStride;
    const float* B = Bb + (size_t)slab * bStride;
    float*       C = Cb + (size_t)slab * cStride;

    int rowBase = blockIdx.x * 64;
    int colBase = blockIdx.y * 64;

    __shared__ float As[16][64], Bs[16][64];
    int tid = threadIdx.x;
    int lm = tid >> 2;
    int lk = (tid & 3) << 2;
    int tx = tid & 15, ty = tid >> 4;

    u64 acc[4][2] = {};
    for (int k0 = 0; k0 < K; k0 += 16) {
        float4 av = *(const float4*)(A + (size_t)(rowBase + lm) * lda + k0 + lk);
        As[lk + 0][lm] = av.x; As[lk + 1][lm] = av.y;
        As[lk + 2][lm] = av.z; As[lk + 3][lm] = av.w;
        float4 bv = *(const float4*)(B + (size_t)(colBase + lm) * ldb + k0 + lk);
        Bs[lk + 0][lm] = bv.x; Bs[lk + 1][lm] = bv.y;
        Bs[lk + 2][lm] = bv.z; Bs[lk + 3][lm] = bv.w;
        __syncthreads();
        #pragma unroll
        for (int k = 0; k < 16; k++) {
            float4 a = *(const float4*)&As[k][ty << 2];
            ulonglong2 b = *(const ulonglong2*)&Bs[k][tx << 2];
            u64 a2;
            a2 = dup2(a.x); fma2(acc[0][0], a2, b.x); fma2(acc[0][1], a2, b.y);
            a2 = dup2(a.y); fma2(acc[1][0], a2, b.x); fma2(acc[1][1], a2, b.y);
            a2 = dup2(a.z); fma2(acc[2][0], a2, b.x); fma2(acc[2][1], a2, b.y);
            a2 = dup2(a.w); fma2(acc[3][0], a2, b.x); fma2(acc[3][1], a2, b.y);
        }
        __syncthreads();
    }
    #pragma unroll
    for (int i = 0; i < 4; i++) {
        int r = rowBase + (ty << 2) + i;
        #pragma unroll
        for (int j2 = 0; j2 < 2; j2++) {
            int c = colBase + (tx << 2) + j2 * 2;
            float2 v = unpack2(acc[i][j2]);
            *(float2*)(C + (size_t)r * ldc + c) = v;
        }
    }
}

// ============================================================
// Small per-(head,slab) finisher
// ============================================================
__global__ void __launch_bounds__(256) assemble2_kernel(const float* __restrict__ Wqkv,
                                                        const float* __restrict__ T,
                                                        float* __restrict__ ET)
{
    int h = blockIdx.x;
    int slab = blockIdx.y;
    const float* Ts = T + (size_t)slab * MM_;
    const float* Wq = Wqkv + (size_t)(0 * H_ + h) * DH_ * M_;
    const float* Wk = Wqkv + (size_t)(1 * H_ + h) * DH_ * M_;

    __shared__ float sT[256][33];
    __shared__ float ktv[32][33];
    int tid = threadIdx.x;

    {
        int m = tid >> 5, d = tid & 31;
        #pragma unroll
        for (int pass = 0; pass < 32; pass++) {
            int mm = pass * 8 + m;
            sT[mm][d] = Ts[(size_t)mm * M_ + h * 32 + d];
        }
    }
    __syncthreads();

    {
        int d  = tid & 31;
        int e0 = (tid >> 5) << 2;
        float acc4[4] = {0.f, 0.f, 0.f, 0.f};
        for (int m = 0; m < 256; m++) {
            float t = sT[m][d];
            #pragma unroll
            for (int ee = 0; ee < 4; ee++)
                acc4[ee] = fmaf(Wk[(size_t)(e0 + ee) * M_ + m], t, acc4[ee]);
        }
        #pragma unroll
        for (int ee = 0; ee < 4; ee++)
            ktv[e0 + ee][d] = acc4[ee];
    }
    __syncthreads();

    float acc3[32];
    #pragma unroll
    for (int d = 0; d < 32; d++) acc3[d] = 0.f;
    for (int e2 = 0; e2 < 32; e2++) {
        float w = Wq[(size_t)e2 * M_ + tid];
        #pragma unroll
        for (int d = 0; d < 32; d++) acc3[d] = fmaf(w, ktv[e2][d], acc3[d]);
    }
    const float scale = 0.17677669529663687f;
    float* ETs = ET + (size_t)slab * MM_;
    #pragma unroll
    for (int d = 0; d < 32; d++)
        ETs[(size_t)(h * 32 + d) * M_ + tid] = scale * acc3[d];
}

// ============================================================
// 128x128 NT fp32 GEMM, f32x2, double-buffered (s2 only).
// ============================================================
__global__ void __launch_bounds__(256) gemm128(
    const float* __restrict__ Ab, int lda, long aStride,
    const float* __restrict__ Bb, int ldb, long bStride,
    float* __restrict__ Cb, int ldc, long cStride,
    int K, int Rlim,
    const float* __restrict__ e1,
    const float* __restrict__ e2, long e2Stride)
{
    int slab = blockIdx.z;
    const float* A = Ab + (size_t)slab * aStride;
    const float* B = Bb + (size_t)slab * bStride;
    float*       C = Cb + (size_t)slab * cStride;
    const float* E2 = e2 + (size_t)slab * e2Stride;

    int rowBase = blockIdx.x * 128;
    int colBase = blockIdx.y * 128;

    __shared__ float As[2][16][128], Bs[2][16][128];
    int tid = threadIdx.x;
    int ldRow = tid >> 1;
    int ldK   = (tid & 1) << 3;
    int tx = tid & 15, ty = tid >> 4;
    int tx4 = tx << 2, ty4 = ty << 2;

    const float* Arow = A + (size_t)(rowBase + ldRow) * lda + ldK;
    const float* Brow = B + (size_t)(colBase + ldRow) * ldb + ldK;
    bool aValid = (rowBase + ldRow) < Rlim;

    const int NT = K >> 4;

    {
        float4 av0, av1;
        if (aValid) { av0 = *(const float4*)Arow; av1 = *(const float4*)(Arow + 4); }
        else        { av0 = make_float4(0.f,0.f,0.f,0.f); av1 = av0; }
        float4 bv0 = *(const float4*)Brow;
        float4 bv1 = *(const float4*)(Brow + 4);
        As[0][ldK+0][ldRow]=av0.x; As[0][ldK+1][ldRow]=av0.y;
        As[0][ldK+2][ldRow]=av0.z; As[0][ldK+3][ldRow]=av0.w;
        As[0][ldK+4][ldRow]=av1.x; As[0][ldK+5][ldRow]=av1.y;
        As[0][ldK+6][ldRow]=av1.z; As[0][ldK+7][ldRow]=av1.w;
        Bs[0][ldK+0][ldRow]=bv0.x; Bs[0][ldK+1][ldRow]=bv0.y;
        Bs[0][ldK+2][ldRow]=bv0.z; Bs[0][ldK+3][ldRow]=bv0.w;
        Bs[0][ldK+4][ldRow]=bv1.x; Bs[0][ldK+5][ldRow]=bv1.y;
        Bs[0][ldK+6][ldRow]=bv1.z; Bs[0][ldK+7][ldRow]=bv1.w;
    }
    __syncthreads();

    u64 acc[8][4] = {};
    for (int it = 0; it < NT; it++) {
        int cur = it & 1;
        bool more = (it + 1 < NT);
        float4 nav0, nav1, nbv0, nbv1;
        if (more) {
            int k0 = (it + 1) << 4;
            if (aValid) { nav0 = *(const float4*)(Arow + k0); nav1 = *(const float4*)(Arow + k0 + 4); }
            else        { nav0 = make_float4(0.f,0.f,0.f,0.f); nav1 = nav0; }
            nbv0 = *(const float4*)(Brow + k0);
            nbv1 = *(const float4*)(Brow + k0 + 4);
        }

        #pragma unroll
        for (int k = 0; k < 16; k++) {
            float4 a0 = *(const float4*)&As[cur][k][ty4];
            float4 a1 = *(const float4*)&As[cur][k][ty4 + 64];
            ulonglong2 b0 = *(const ulonglong2*)&Bs[cur][k][tx4];
            ulonglong2 b1 = *(const ulonglong2*)&Bs[cur][k][tx4 + 64];
            u64 a2;
            a2 = dup2(a0.x); fma2(acc[0][0],a2,b0.x); fma2(acc[0][1],a2,b0.y); fma2(acc[0][2],a2,b1.x); fma2(acc[0][3],a2,b1.y);
            a2 = dup2(a0.y); fma2(acc[1][0],a2,b0.x); fma2(acc[1][1],a2,b0.y); fma2(acc[1][2],a2,b1.x); fma2(acc[1][3],a2,b1.y);
            a2 = dup2(a0.z); fma2(acc[2][0],a2,b0.x); fma2(acc[2][1],a2,b0.y); fma2(acc[2][2],a2,b1.x); fma2(acc[2][3],a2,b1.y);
            a2 = dup2(a0.w); fma2(acc[3][0],a2,b0.x); fma2(acc[3][1],a2,b0.y); fma2(acc[3][2],a2,b1.x); fma2(acc[3][3],a2,b1.y);
            a2 = dup2(a1.x); fma2(acc[4][0],a2,b0.x); fma2(acc[4][1],a2,b0.y); fma2(acc[4][2],a2,b1.x); fma2(acc[4][3],a2,b1.y);
            a2 = dup2(a1.y); fma2(acc[5][0],a2,b0.x); fma2(acc[5][1],a2,b0.y); fma2(acc[5][2],a2,b1.x); fma2(acc[5][3],a2,b1.y);
            a2 = dup2(a1.z); fma2(acc[6][0],a2,b0.x); fma2(acc[6][1],a2,b0.y); fma2(acc[6][2],a2,b1.x); fma2(acc[6][3],a2,b1.y);
            a2 = dup2(a1.w); fma2(acc[7][0],a2,b0.x); fma2(acc[7][1],a2,b0.y); fma2(acc[7][2],a2,b1.x); fma2(acc[7][3],a2,b1.y);
        }

        if (more) {
            int nxt = cur ^ 1;
            As[nxt][ldK+0][ldRow]=nav0.x; As[nxt][ldK+1][ldRow]=nav0.y;
            As[nxt][ldK+2][ldRow]=nav0.z; As[nxt][ldK+3][ldRow]=nav0.w;
            As[nxt][ldK+4][ldRow]=nav1.x; As[nxt][ldK+5][ldRow]=nav1.y;
            As[nxt][ldK+6][ldRow]=nav1.z; As[nxt][ldK+7][ldRow]=nav1.w;
            Bs[nxt][ldK+0][ldRow]=nbv0.x; Bs[nxt][ldK+1][ldRow]=nbv0.y;
            Bs[nxt][ldK+2][ldRow]=nbv0.z; Bs[nxt][ldK+3][ldRow]=nbv0.w;
            Bs[nxt][ldK+4][ldRow]=nbv1.x; Bs[nxt][ldK+5][ldRow]=nbv1.y;
            Bs[nxt][ldK+6][ldRow]=nbv1.z; Bs[nxt][ldK+7][ldRow]=nbv1.w;
        }
        __syncthreads();
    }

    #pragma unroll
    for (int i = 0; i < 8; i++) {
        int r = rowBase + ty4 + (i & 3) + ((i >> 2) << 6);
        if (r >= Rlim) continue;
        #pragma unroll
        for (int j2 = 0; j2 < 4; j2++) {
            int c = colBase + tx4 + ((j2 & 1) << 1) + ((j2 >> 1) << 6);
            float2 v = unpack2(acc[i][j2]);
            size_t idx = (size_t)r * ldc + c;
            v.x = v.x * e1[c]     + E2[idx];
            v.y = v.y * e1[c + 1] + E2[idx + 1];
            *(float2*)(C + idx) = v;
        }
    }
}

// ============================================================
// 3-product split-bf16 tensor-core NT GEMM (m16n8k16).
// fp32 in GMEM; split to two packed-bf16x2 planes at smem store.
// 128x128 CTA, 8 warps (2x4), 64x32 per warp.
//   mode 1: C = gelu(acc + bias[c])
//   mode 2: C = acc + bias[c] + resid[r,c]
// smem row: [hi kp0..7 | lo kp0..7 | pad], stride ST=20 u32
// (g*20+t)%32 distinct for g<8,t<4 -> conflict-free fragments.
// ============================================================
#define ST 20
__device__ __forceinline__ void split_store8(uint32_t* rowp, int kp0,
                                             float4 f0, float4 f1)
{
    uint32_t u0 = __float_as_uint(f0.x), u1 = __float_as_uint(f0.y);
    uint32_t u2 = __float_as_uint(f0.z), u3 = __float_as_uint(f0.w);
    uint32_t u4 = __float_as_uint(f1.x), u5 = __float_as_uint(f1.y);
    uint32_t u6 = __float_as_uint(f1.z), u7 = __float_as_uint(f1.w);
    uint4 hp;
    hp.x = __byte_perm(u0, u1, 0x7632);
    hp.y = __byte_perm(u2, u3, 0x7632);
    hp.z = __byte_perm(u4, u5, 0x7632);
    hp.w = __byte_perm(u6, u7, 0x7632);
    uint4 lp;
    lp.x = pack_lo2(f0.x - __uint_as_float(u0 & 0xFFFF0000u),
                    f0.y - __uint_as_float(u1 & 0xFFFF0000u));
    lp.y = pack_lo2(f0.z - __uint_as_float(u2 & 0xFFFF0000u),
                    f0.w - __uint_as_float(u3 & 0xFFFF0000u));
    lp.z = pack_lo2(f1.x - __uint_as_float(u4 & 0xFFFF0000u),
                    f1.y - __uint_as_float(u5 & 0xFFFF0000u));
    lp.w = pack_lo2(f1.z - __uint_as_float(u6 & 0xFFFF0000u),
                    f1.w - __uint_as_float(u7 & 0xFFFF0000u));
    *(uint4*)(rowp + kp0)     = hp;
    *(uint4*)(rowp + 8 + kp0) = lp;
}

__global__ void __launch_bounds__(256) bf16_gemm(
    const float* __restrict__ A, int lda,
    const float* __restrict__ B, int ldb,
    float* __restrict__ C, int ldc,
    int K, int Rlim, int mode,
    const float* __restrict__ bias,
    const float* __restrict__ resid)
{
    __shared__ uint32_t sA[2][128 * ST], sB[2][128 * ST];   // 40 KB total
    int tid = threadIdx.x;
    int rowBase = blockIdx.x * 128, colBase = blockIdx.y * 128;

    int ldRow = tid >> 1;            // 0..127
    int ldK   = (tid & 1) << 3;      // 0 or 8
    int kp0   = (tid & 1) << 2;      // 0 or 4 (k-pair offset)
    const float* Arow = A + (size_t)(rowBase + ldRow) * lda + ldK;
    const float* Brow = B + (size_t)(colBase + ldRow) * ldb + ldK;
    bool aValid = (rowBase + ldRow) < Rlim;

    int lane = tid & 31, warp = tid >> 5;
    int wRow = (warp >> 2) << 6;     // 0 or 64
    int wCol = (warp & 3) << 5;      // 0,32,64,96
    int g = lane >> 2, t = lane & 3;

    const int NT = K >> 4;
    const float4 z4 = make_float4(0.f, 0.f, 0.f, 0.f);

    // preload tile 0
    {
        float4 a0 = aValid ? *(const float4*)Arow : z4;
        float4 a1 = aValid ? *(const float4*)(Arow + 4) : z4;
        split_store8(&sA[0][ldRow * ST], kp0, a0, a1);
        float4 b0 = *(const float4*)Brow;
        float4 b1 = *(const float4*)(Brow + 4);
        split_store8(&sB[0][ldRow * ST], kp0, b0, b1);
    }
    __syncthreads();

    float acc[4][4][4];
    #pragma unroll
    for (int i = 0; i < 4; i++)
        #pragma unroll
        for (int j = 0; j < 4; j++)
            #pragma unroll
            for (int q = 0; q < 4; q++) acc[i][j][q] = 0.f;

    for (int it = 0; it < NT; it++) {
        int cur = it & 1;
        bool more = (it + 1 < NT);
        float4 na0, na1, nb0, nb1;
        if (more) {
            int k0 = (it + 1) << 4;
            na0 = aValid ? *(const float4*)(Arow + k0) : z4;
            na1 = aValid ? *(const float4*)(Arow + k0 + 4) : z4;
            nb0 = *(const float4*)(Brow + k0);
            nb1 = *(const float4*)(Brow + k0 + 4);
        }

        const uint32_t* sa = sA[cur];
        const uint32_t* sb = sB[cur];

        // fragments: one k16 MMA step per tile
        uint32_t ahi[4][4], alo[4][4];
        #pragma unroll
        for (int mb = 0; mb < 4; mb++) {
            int b0i = (wRow + (mb << 4) + g) * ST;
            int b1i = b0i + (ST << 3);             // +8 rows
            ahi[mb][0] = sa[b0i + t];     ahi[mb][1] = sa[b1i + t];
            ahi[mb][2] = sa[b0i + t + 4]; ahi[mb][3] = sa[b1i + t + 4];
            alo[mb][0] = sa[b0i + 8 + t];     alo[mb][1] = sa[b1i + 8 + t];
            alo[mb][2] = sa[b0i + 8 + t + 4]; alo[mb][3] = sa[b1i + 8 + t + 4];
        }
        uint32_t bhi[4][2], blo[4][2];
        #pragma unroll
        for (int nb = 0; nb < 4; nb++) {
            int bi = (wCol + (nb << 3) + g) * ST;
            bhi[nb][0] = sb[bi + t];     bhi[nb][1] = sb[bi + t + 4];
            blo[nb][0] = sb[bi + 8 + t]; blo[nb][1] = sb[bi + 8 + t + 4];
        }
        // ah*bl
        #pragma unroll
        for (int mb = 0; mb < 4; mb++)
            #pragma unroll
            for (int nb = 0; nb < 4; nb++)
                mma_bf16(acc[mb][nb], ahi[mb][0], ahi[mb][1], ahi[mb][2], ahi[mb][3],
                         blo[nb][0], blo[nb][1]);
        // al*bh
        #pragma unroll
        for (int mb = 0; mb < 4; mb++)
            #pragma unroll
            for (int nb = 0; nb < 4; nb++)
                mma_bf16(acc[mb][nb], alo[mb][0], alo[mb][1], alo[mb][2], alo[mb][3],
                         bhi[nb][0], bhi[nb][1]);
        // ah*bh
        #pragma unroll
        for (int mb = 0; mb < 4; mb++)
            #pragma unroll
            for (int nb = 0; nb < 4; nb++)
                mma_bf16(acc[mb][nb], ahi[mb][0], ahi[mb][1], ahi[mb][2], ahi[mb][3],
                         bhi[nb][0], bhi[nb][1]);

        if (more) {
            int nxt = cur ^ 1;
            split_store8(&sA[nxt][ldRow * ST], kp0, na0, na1);
            split_store8(&sB[nxt][ldRow * ST], kp0, nb0, nb1);
        }
        __syncthreads();
    }

    // epilogue
    const float inv_sqrt2 = 0.7071067811865475f;
    #pragma unroll
    for (int mb = 0; mb < 4; mb++) {
        int r0 = rowBase + wRow + (mb << 4) + g;
        #pragma unroll
        for (int half = 0; half < 2; half++) {
            int r = r0 + half * 8;
            if (r >= Rlim) continue;
            #pragma unroll
            for (int nb = 0; nb < 4; nb++) {
                int c = colBase + wCol + (nb << 3) + (t << 1);
                float vx = acc[mb][nb][half * 2 + 0];
                float vy = acc[mb][nb][half * 2 + 1];
                if (mode == 1) {
                    vx += bias[c];
                    vy += bias[c + 1];
                    vx = 0.5f * vx * (1.0f + erff(vx * inv_sqrt2));
                    vy = 0.5f * vy * (1.0f + erff(vy * inv_sqrt2));
                } else {
                    const float* rr = resid + (size_t)r * ldc + c;
                    vx += bias[c]     + rr[0];
                    vy += bias[c + 1] + rr[1];
                }
                *(float2*)(C + (size_t)r * ldc + c) = make_float2(vx, vy);
            }
        }
    }
}

// ============================================================
// Launch
// ============================================================
extern "C" void kernel_launch(void* const* d_in, const int* in_sizes, int n_in,
                              void* d_out, int out_size)
{
    (void)in_sizes; (void)n_in; (void)out_size;
    const float* savespace = (const float*)d_in[1];
    const float* Wqkv      = (const float*)d_in[2];
    const float* Wo        = (const float*)d_in[3];
    const float* ln1_g     = (const float*)d_in[4];
    const float* ln1_b     = (const float*)d_in[5];
    const float* ln2_g     = (const float*)d_in[6];
    const float* ln2_b     = (const float*)d_in[7];
    const float* fc1_w     = (const float*)d_in[8];
    const float* fc1_b     = (const float*)d_in[9];
    const float* fc2_w     = (const float*)d_in[10];
    const float* fc2_b     = (const float*)d_in[11];
    float* out = (float*)d_out;

    float *p_sln, *p_s2, *p_hln, *p_h1, *p_G, *p_Gp, *p_T, *p_ET, *p_ws;
    cudaGetSymbolAddress((void**)&p_sln, g_sln);
    cudaGetSymbolAddress((void**)&p_s2,  g_s2);
    cudaGetSymbolAddress((void**)&p_hln, g_hln);
    cudaGetSymbolAddress((void**)&p_h1,  g_h1);
    cudaGetSymbolAddress((void**)&p_G,   g_G);
    cudaGetSymbolAddress((void**)&p_Gp,  g_Gp);
    cudaGetSymbolAddress((void**)&p_T,   g_T);
    cudaGetSymbolAddress((void**)&p_ET,  g_ET);
    cudaGetSymbolAddress((void**)&p_ws,  g_wosum);

    const long SLAB = (long)J_ * M_;
    const long MM   = MM_;

    // 1) layernorm1
    ln_kernel<<<RTOT, 256>>>(savespace, ln1_g, ln1_b, p_sln);
    // 2) Gram partials + reduce
    gram_kernel<<<dim3(4, 4, NSLAB * NCH), 256>>>(p_sln, p_Gp);
    gram_reduce<<<dim3(64, NSLAB), 256>>>(p_Gp, p_G);
    // 3) Wo row sums
    rowsum_kernel<<<32, 256>>>(Wo, p_ws);
    // 4) T = G @ Wv_full^T per slab
    gemm64<<<dim3(4, 4, NSLAB), 256>>>(
        p_G, M_, MM,  Wqkv + 2 * H_ * DH_ * M_, M_, 0,  p_T, M_, MM, M_);
    // 5) finish ET per (head, slab)
    assemble2_kernel<<<dim3(H_, NSLAB), 256>>>(Wqkv, p_T, p_ET);
    // 6) s2 = wosum * (s_ln @ E) + savespace
    gemm128<<<dim3(9, 2, NSLAB), 256>>>(
        p_sln, M_, SLAB,  p_ET, M_, MM,  p_s2, M_, SLAB,
        M_, J_, p_ws, savespace, SLAB);
    // 7) layernorm2
    ln_kernel<<<RTOT, 256>>>(p_s2, ln2_g, ln2_b, p_hln);
    // 8) h1 = gelu(hln @ fc1_w^T + b1)   [split-bf16 m16n8k16]
    bf16_gemm<<<dim3(129, 8), 256>>>(
        p_hln, M_, fc1_w, M_, p_h1, FF_,
        M_, RTOT, 1, fc1_b, (const float*)0);
    // 9) out = h1 @ fc2_w^T + b2 + s2    [split-bf16 m16n8k16]
    bf16_gemm<<<dim3(129, 2), 256>>>(
        p_h1, FF_, fc2_w, FF_, out, M_,
        FF_, RTOT, 2, fc2_b, p_s2);
}

// round 11
// speedup vs baseline: 2.1781x; 1.0243x over previous
#include <cuda_runtime.h>
#include <math.h>
#include <cstdint>

// Shapes (fixed by the problem)
#define B_    2
#define I_    8
#define J_    1025
#define M_    256
#define H_    8
#define DH_   32
#define NSLAB 16              // B_*I_
#define RTOT  (NSLAB * J_)    // 16400
#define FF_   1024            // 4*M
#define NCH   5               // gram J-chunks
#define MM_   (M_ * M_)

typedef unsigned long long u64;

// ---- scratch (static __device__ arrays; no runtime allocation) ----
__device__ float g_sln[RTOT * M_];
__device__ float g_s2 [RTOT * M_];
__device__ float g_hln[RTOT * M_];
__device__ float g_h1 [(size_t)RTOT * FF_];
__device__ float g_G  [NSLAB * MM_];
__device__ float g_Gp [NCH * NSLAB * MM_];     // gram partials
__device__ float g_T  [NSLAB * MM_];
__device__ float g_ET [NSLAB * MM_];
__device__ float g_wosum[M_];

// ---- f32x2 packed-FMA helpers ----
__device__ __forceinline__ u64 dup2(float x) {
    u64 r; asm("mov.b64 %0, {%1,%1};" : "=l"(r) : "f"(x)); return r;
}
__device__ __forceinline__ void fma2(u64& d, u64 a, u64 b) {
    asm("fma.rn.f32x2 %0, %1, %2, %0;" : "+l"(d) : "l"(a), "l"(b));
}
__device__ __forceinline__ float2 unpack2(u64 v) {
    float2 r; asm("mov.b64 {%0,%1}, %2;" : "=f"(r.x), "=f"(r.y) : "l"(v)); return r;
}

// ---- bf16 mma helper (m16n8k16, sm_80+) ----
__device__ __forceinline__ void mma_bf16(float* c,
    uint32_t a0, uint32_t a1, uint32_t a2, uint32_t a3,
    uint32_t b0, uint32_t b1)
{
    asm("mma.sync.aligned.m16n8k16.row.col.f32.bf16.bf16.f32 "
        "{%0,%1,%2,%3}, {%4,%5,%6,%7}, {%8,%9}, {%0,%1,%2,%3};"
        : "+f"(c[0]), "+f"(c[1]), "+f"(c[2]), "+f"(c[3])
        : "r"(a0), "r"(a1), "r"(a2), "r"(a3), "r"(b0), "r"(b1));
}
__device__ __forceinline__ uint32_t pack_lo2(float lo0, float lo1) {
    uint32_t r;
    asm("cvt.rn.bf16x2.f32 %0, %1, %2;" : "=r"(r) : "f"(lo1), "f"(lo0));
    return r;
}

// ============================================================
// LayerNorm over last dim M_=256, one block (256 thr) per row
// ============================================================
__global__ void ln_kernel(const float* __restrict__ x,
                          const float* __restrict__ g,
                          const float* __restrict__ b,
                          float* __restrict__ out)
{
    int row = blockIdx.x;
    const float* xr = x + (size_t)row * M_;
    int t = threadIdx.x;
    float v = xr[t];

    __shared__ float sm[8];
    float s = v;
    #pragma unroll
    for (int o = 16; o > 0; o >>= 1) s += __shfl_xor_sync(0xffffffffu, s, o);
    if ((t & 31) == 0) sm[t >> 5] = s;
    __syncthreads();
    float mean = 0.f;
    #pragma unroll
    for (int i = 0; i < 8; i++) mean += sm[i];
    mean *= (1.0f / M_);
    __syncthreads();
    float d = v - mean;
    float q = d * d;
    #pragma unroll
    for (int o = 16; o > 0; o >>= 1) q += __shfl_xor_sync(0xffffffffu, q, o);
    if ((t & 31) == 0) sm[t >> 5] = q;
    __syncthreads();
    float var = 0.f;
    #pragma unroll
    for (int i = 0; i < 8; i++) var += sm[i];
    var *= (1.0f / M_);

    out[(size_t)row * M_ + t] = d * rsqrtf(var + 1e-5f) * g[t] + b[t];
}

// ============================================================
// Wo row sums — one warp per row
// ============================================================
__global__ void rowsum_kernel(const float* __restrict__ Wo, float* __restrict__ ws)
{
    int warp = threadIdx.x >> 5, lane = threadIdx.x & 31;
    int n = blockIdx.x * 8 + warp;
    const float* row = Wo + (size_t)n * M_;
    float s = 0.f;
    #pragma unroll
    for (int m = lane; m < M_; m += 32) s += row[m];
    #pragma unroll
    for (int o = 16; o > 0; o >>= 1) s += __shfl_xor_sync(0xffffffffu, s, o);
    if (lane == 0) ws[n] = s;
}

// ============================================================
// Gram partials: J split in NCH chunks
// ============================================================
__global__ void __launch_bounds__(256) gram_kernel(const float* __restrict__ sln,
                                                   float* __restrict__ Gp)
{
    if (blockIdx.y < blockIdx.x) return;
    int zc = blockIdx.z;
    int slab = zc / NCH;
    int ch = zc - slab * NCH;
    const float* A = sln + (size_t)slab * J_ * M_;
    int p0 = blockIdx.x * 64, q0 = blockIdx.y * 64;

    int t0 = ch * 13, t1 = t0 + 13;

    __shared__ float As[2][16][64], Bs[2][16][64];
    int tid = threadIdx.x;
    int jj = tid >> 4;
    int cq = (tid & 15) << 2;
    int tx = tid & 15, ty = tid >> 4;

    float4 av, bv;
    {
        int j = t0 * 16 + jj;
        if (j < J_) {
            av = *(const float4*)(A + (size_t)j * M_ + p0 + cq);
            bv = *(const float4*)(A + (size_t)j * M_ + q0 + cq);
        } else { av = make_float4(0.f,0.f,0.f,0.f); bv = av; }
    }
    *(float4*)&As[0][jj][cq] = av;
    *(float4*)&Bs[0][jj][cq] = bv;
    __syncthreads();

    u64 acc[4][2] = {};
    for (int it = t0; it < t1; it++) {
        int cur = (it - t0) & 1;
        float4 nav, nbv;
        bool more = (it + 1 < t1);
        if (more) {
            int j = (it + 1) * 16 + jj;
            if (j < J_) {
                nav = *(const float4*)(A + (size_t)j * M_ + p0 + cq);
                nbv = *(const float4*)(A + (size_t)j * M_ + q0 + cq);
            } else { nav = make_float4(0.f,0.f,0.f,0.f); nbv = nav; }
        }
        #pragma unroll
        for (int k = 0; k < 16; k++) {
            float4 a = *(const float4*)&As[cur][k][ty << 2];
            ulonglong2 b = *(const ulonglong2*)&Bs[cur][k][tx << 2];
            u64 a2;
            a2 = dup2(a.x); fma2(acc[0][0], a2, b.x); fma2(acc[0][1], a2, b.y);
            a2 = dup2(a.y); fma2(acc[1][0], a2, b.x); fma2(acc[1][1], a2, b.y);
            a2 = dup2(a.z); fma2(acc[2][0], a2, b.x); fma2(acc[2][1], a2, b.y);
            a2 = dup2(a.w); fma2(acc[3][0], a2, b.x); fma2(acc[3][1], a2, b.y);
        }
        if (more) {
            *(float4*)&As[cur ^ 1][jj][cq] = nav;
            *(float4*)&Bs[cur ^ 1][jj][cq] = nbv;
        }
        __syncthreads();
    }
    float* Gs = Gp + (size_t)zc * MM_;
    #pragma unroll
    for (int i = 0; i < 4; i++) {
        int p = p0 + (ty << 2) + i;
        #pragma unroll
        for (int j2 = 0; j2 < 2; j2++) {
            float2 v = unpack2(acc[i][j2]);
            int q = q0 + (tx << 2) + j2 * 2;
            Gs[(size_t)p * M_ + q]     = v.x;
            Gs[(size_t)p * M_ + q + 1] = v.y;
            Gs[(size_t)q * M_ + p]       = v.x;
            Gs[(size_t)(q + 1) * M_ + p] = v.y;
        }
    }
}

// ============================================================
// Gram reduce
// ============================================================
__global__ void gram_reduce(const float* __restrict__ Gp, float* __restrict__ G)
{
    int slab = blockIdx.y;
    int idx = (blockIdx.x * 256 + threadIdx.x) * 4;
    const float* base = Gp + (size_t)slab * NCH * MM_ + idx;
    float4 s = *(const float4*)base;
    #pragma unroll
    for (int ch = 1; ch < NCH; ch++) {
        float4 v = *(const float4*)(base + (size_t)ch * MM_);
        s.x += v.x; s.y += v.y; s.z += v.z; s.w += v.w;
    }
    *(float4*)(G + (size_t)slab * MM_ + idx) = s;
}

// ============================================================
// 64x64 NT GEMM (T = G @ Wv^T)
// ============================================================
__global__ void __launch_bounds__(256) gemm64(
    const float* __restrict__ Ab, int lda, long aStride,
    const float* __restrict__ Bb, int ldb, long bStride,
    float* __restrict__ Cb, int ldc, long cStride, int K)
{
    int slab = blockIdx.z;
    const float* A = Ab + (size_t)slab * aStride;
    const float* B = Bb + (size_t)slab * bStride;
    float*       C = Cb + (size_t)slab * cStride;

    int rowBase = blockIdx.x * 64;
    int colBase = blockIdx.y * 64;

    __shared__ float As[16][64], Bs[16][64];
    int tid = threadIdx.x;
    int lm = tid >> 2;
    int lk = (tid & 3) << 2;
    int tx = tid & 15, ty = tid >> 4;

    u64 acc[4][2] = {};
    for (int k0 = 0; k0 < K; k0 += 16) {
        float4 av = *(const float4*)(A + (size_t)(rowBase + lm) * lda + k0 + lk);
        As[lk + 0][lm] = av.x; As[lk + 1][lm] = av.y;
        As[lk + 2][lm] = av.z; As[lk + 3][lm] = av.w;
        float4 bv = *(const float4*)(B + (size_t)(colBase + lm) * ldb + k0 + lk);
        Bs[lk + 0][lm] = bv.x; Bs[lk + 1][lm] = bv.y;
        Bs[lk + 2][lm] = bv.z; Bs[lk + 3][lm] = bv.w;
        __syncthreads();
        #pragma unroll
        for (int k = 0; k < 16; k++) {
            float4 a = *(const float4*)&As[k][ty << 2];
            ulonglong2 b = *(const ulonglong2*)&Bs[k][tx << 2];
            u64 a2;
            a2 = dup2(a.x); fma2(acc[0][0], a2, b.x); fma2(acc[0][1], a2, b.y);
            a2 = dup2(a.y); fma2(acc[1][0], a2, b.x); fma2(acc[1][1], a2, b.y);
            a2 = dup2(a.z); fma2(acc[2][0], a2, b.x); fma2(acc[2][1], a2, b.y);
            a2 = dup2(a.w); fma2(acc[3][0], a2, b.x); fma2(acc[3][1], a2, b.y);
        }
        __syncthreads();
    }
    #pragma unroll
    for (int i = 0; i < 4; i++) {
        int r = rowBase + (ty << 2) + i;
        #pragma unroll
        for (int j2 = 0; j2 < 2; j2++) {
            int c = colBase + (tx << 2) + j2 * 2;
            float2 v = unpack2(acc[i][j2]);
            *(float2*)(C + (size_t)r * ldc + c) = v;
        }
    }
}

// ============================================================
// Small per-(head,slab) finisher
// ============================================================
__global__ void __launch_bounds__(256) assemble2_kernel(const float* __restrict__ Wqkv,
                                                        const float* __restrict__ T,
                                                        float* __restrict__ ET)
{
    int h = blockIdx.x;
    int slab = blockIdx.y;
    const float* Ts = T + (size_t)slab * MM_;
    const float* Wq = Wqkv + (size_t)(0 * H_ + h) * DH_ * M_;
    const float* Wk = Wqkv + (size_t)(1 * H_ + h) * DH_ * M_;

    __shared__ float sT[256][33];
    __shared__ float ktv[32][33];
    int tid = threadIdx.x;

    {
        int m = tid >> 5, d = tid & 31;
        #pragma unroll
        for (int pass = 0; pass < 32; pass++) {
            int mm = pass * 8 + m;
            sT[mm][d] = Ts[(size_t)mm * M_ + h * 32 + d];
        }
    }
    __syncthreads();

    {
        int d  = tid & 31;
        int e0 = (tid >> 5) << 2;
        float acc4[4] = {0.f, 0.f, 0.f, 0.f};
        for (int m = 0; m < 256; m++) {
            float t = sT[m][d];
            #pragma unroll
            for (int ee = 0; ee < 4; ee++)
                acc4[ee] = fmaf(Wk[(size_t)(e0 + ee) * M_ + m], t, acc4[ee]);
        }
        #pragma unroll
        for (int ee = 0; ee < 4; ee++)
            ktv[e0 + ee][d] = acc4[ee];
    }
    __syncthreads();

    float acc3[32];
    #pragma unroll
    for (int d = 0; d < 32; d++) acc3[d] = 0.f;
    for (int e2 = 0; e2 < 32; e2++) {
        float w = Wq[(size_t)e2 * M_ + tid];
        #pragma unroll
        for (int d = 0; d < 32; d++) acc3[d] = fmaf(w, ktv[e2][d], acc3[d]);
    }
    const float scale = 0.17677669529663687f;
    float* ETs = ET + (size_t)slab * MM_;
    #pragma unroll
    for (int d = 0; d < 32; d++)
        ETs[(size_t)(h * 32 + d) * M_ + tid] = scale * acc3[d];
}

// ============================================================
// 3-product split-bf16 tensor-core NT GEMM (m16n8k16).
// fp32 in GMEM; split at smem store into interleaved pair-groups:
//   row (16 u32 + 4 pad): [hi_2i, hi_2i+1, lo_2i, lo_2i+1] x4
// k-permutation (hw pair q -> storage pair 2q / 2(q-4)+1) applied
// identically to A and B, so fragments are single LDS.128s.
// 128x128 CTA, 8 warps (2x4), 64x32 per warp.
//   mode 0: C = acc * e1[c] + e2[slab][r,c]     (s2; batched)
//   mode 1: C = gelu(acc + e1[c])               (fc1)
//   mode 2: C = acc + e1[c] + e2[r,c]           (fc2 + resid)
// ============================================================
#define ST 20
__device__ __forceinline__ void split_store8(uint32_t* rowp, int woff,
                                             float4 f0, float4 f1)
{
    uint32_t u0 = __float_as_uint(f0.x), u1 = __float_as_uint(f0.y);
    uint32_t u2 = __float_as_uint(f0.z), u3 = __float_as_uint(f0.w);
    uint32_t u4 = __float_as_uint(f1.x), u5 = __float_as_uint(f1.y);
    uint32_t u6 = __float_as_uint(f1.z), u7 = __float_as_uint(f1.w);
    uint32_t h01 = __byte_perm(u0, u1, 0x7632);   // hi pair p0
    uint32_t h23 = __byte_perm(u2, u3, 0x7632);   // hi pair p1
    uint32_t h45 = __byte_perm(u4, u5, 0x7632);   // hi pair p2
    uint32_t h67 = __byte_perm(u6, u7, 0x7632);   // hi pair p3
    uint32_t l01 = pack_lo2(f0.x - __uint_as_float(u0 & 0xFFFF0000u),
                            f0.y - __uint_as_float(u1 & 0xFFFF0000u));
    uint32_t l23 = pack_lo2(f0.z - __uint_as_float(u2 & 0xFFFF0000u),
                            f0.w - __uint_as_float(u3 & 0xFFFF0000u));
    uint32_t l45 = pack_lo2(f1.x - __uint_as_float(u4 & 0xFFFF0000u),
                            f1.y - __uint_as_float(u5 & 0xFFFF0000u));
    uint32_t l67 = pack_lo2(f1.z - __uint_as_float(u6 & 0xFFFF0000u),
                            f1.w - __uint_as_float(u7 & 0xFFFF0000u));
    // group layout: [hi_p, hi_p+1, lo_p, lo_p+1]
    *(uint4*)(rowp + woff)     = make_uint4(h01, h23, l01, l23);
    *(uint4*)(rowp + woff + 4) = make_uint4(h45, h67, l45, l67);
}

__global__ void __launch_bounds__(256) bf16_gemm(
    const float* __restrict__ Ab, int lda, long aStr,
    const float* __restrict__ Bb, int ldb, long bStr,
    float* __restrict__ Cb, int ldc, long cStr,
    int K, int Rlim, int mode,
    const float* __restrict__ e1,
    const float* __restrict__ e2b, long e2Str)
{
    __shared__ uint32_t sA[2][128 * ST], sB[2][128 * ST];   // 40 KB
    int tid = threadIdx.x;
    int slab = blockIdx.z;
    const float* A = Ab + (size_t)slab * aStr;
    const float* B = Bb + (size_t)slab * bStr;
    float*       C = Cb + (size_t)slab * cStr;
    const float* E2 = e2b ? (e2b + (size_t)slab * e2Str) : (const float*)0;

    int rowBase = blockIdx.x * 128, colBase = blockIdx.y * 128;

    int ldRow = tid >> 1;            // 0..127
    int ldK   = (tid & 1) << 3;      // 0 or 8
    int woff  = (tid & 1) << 3;      // word offset 0 or 8
    const float* Arow = A + (size_t)(rowBase + ldRow) * lda + ldK;
    const float* Brow = B + (size_t)(colBase + ldRow) * ldb + ldK;
    bool aValid = (rowBase + ldRow) < Rlim;

    int lane = tid & 31, warp = tid >> 5;
    int wRow = (warp >> 2) << 6;     // 0 or 64
    int wCol = (warp & 3) << 5;      // 0,32,64,96
    int g = lane >> 2, t = lane & 3;

    const int NT = K >> 4;
    const float4 z4 = make_float4(0.f, 0.f, 0.f, 0.f);

    // preload tile 0
    {
        float4 a0 = aValid ? *(const float4*)Arow : z4;
        float4 a1 = aValid ? *(const float4*)(Arow + 4) : z4;
        split_store8(&sA[0][ldRow * ST], woff, a0, a1);
        float4 b0 = *(const float4*)Brow;
        float4 b1 = *(const float4*)(Brow + 4);
        split_store8(&sB[0][ldRow * ST], woff, b0, b1);
    }
    __syncthreads();

    float acc[4][4][4];
    #pragma unroll
    for (int i = 0; i < 4; i++)
        #pragma unroll
        for (int j = 0; j < 4; j++)
            #pragma unroll
            for (int q = 0; q < 4; q++) acc[i][j][q] = 0.f;

    for (int it = 0; it < NT; it++) {
        int cur = it & 1;
        bool more = (it + 1 < NT);
        float4 na0, na1, nb0, nb1;
        if (more) {
            int k0 = (it + 1) << 4;
            na0 = aValid ? *(const float4*)(Arow + k0) : z4;
            na1 = aValid ? *(const float4*)(Arow + k0 + 4) : z4;
            nb0 = *(const float4*)(Brow + k0);
            nb1 = *(const float4*)(Brow + k0 + 4);
        }

        const uint32_t* sa = sA[cur];
        const uint32_t* sb = sB[cur];

        // fragments via LDS.128 (group t of each row)
        uint4 avlo[4], avhi_[4];   // row g, row g+8 per mb
        uint32_t ahi[4][4], alo[4][4];
        #pragma unroll
        for (int mb = 0; mb < 4; mb++) {
            const uint32_t* r0p = sa + (wRow + (mb << 4) + g) * ST + (t << 2);
            uint4 v0 = *(const uint4*)r0p;
            uint4 v1 = *(const uint4*)(r0p + (ST << 3));   // +8 rows
            ahi[mb][0] = v0.x; ahi[mb][1] = v1.x;
            ahi[mb][2] = v0.y; ahi[mb][3] = v1.y;
            alo[mb][0] = v0.z; alo[mb][1] = v1.z;
            alo[mb][2] = v0.w; alo[mb][3] = v1.w;
        }
        uint32_t bhi[4][2], blo[4][2];
        #pragma unroll
        for (int nb = 0; nb < 4; nb++) {
            uint4 v = *(const uint4*)(sb + (wCol + (nb << 3) + g) * ST + (t << 2));
            bhi[nb][0] = v.x; bhi[nb][1] = v.y;
            blo[nb][0] = v.z; blo[nb][1] = v.w;
        }
        // ah*bl
        #pragma unroll
        for (int mb = 0; mb < 4; mb++)
            #pragma unroll
            for (int nb = 0; nb < 4; nb++)
                mma_bf16(acc[mb][nb], ahi[mb][0], ahi[mb][1], ahi[mb][2], ahi[mb][3],
                         blo[nb][0], blo[nb][1]);
        // al*bh
        #pragma unroll
        for (int mb = 0; mb < 4; mb++)
            #pragma unroll
            for (int nb = 0; nb < 4; nb++)
                mma_bf16(acc[mb][nb], alo[mb][0], alo[mb][1], alo[mb][2], alo[mb][3],
                         bhi[nb][0], bhi[nb][1]);
        // ah*bh
        #pragma unroll
        for (int mb = 0; mb < 4; mb++)
            #pragma unroll
            for (int nb = 0; nb < 4; nb++)
                mma_bf16(acc[mb][nb], ahi[mb][0], ahi[mb][1], ahi[mb][2], ahi[mb][3],
                         bhi[nb][0], bhi[nb][1]);

        if (more) {
            int nxt = cur ^ 1;
            split_store8(&sA[nxt][ldRow * ST], woff, na0, na1);
            split_store8(&sB[nxt][ldRow * ST], woff, nb0, nb1);
        }
        __syncthreads();
    }

    // epilogue
    const float inv_sqrt2 = 0.7071067811865475f;
    #pragma unroll
    for (int mb = 0; mb < 4; mb++) {
        int r0 = rowBase + wRow + (mb << 4) + g;
        #pragma unroll
        for (int half = 0; half < 2; half++) {
            int r = r0 + half * 8;
            if (r >= Rlim) continue;
            #pragma unroll
            for (int nb = 0; nb < 4; nb++) {
                int c = colBase + wCol + (nb << 3) + (t << 1);
                float vx = acc[mb][nb][half * 2 + 0];
                float vy = acc[mb][nb][half * 2 + 1];
                if (mode == 0) {
                    const float* rr = E2 + (size_t)r * ldc + c;
                    vx = vx * e1[c]     + rr[0];
                    vy = vy * e1[c + 1] + rr[1];
                } else if (mode == 1) {
                    vx += e1[c];
                    vy += e1[c + 1];
                    vx = 0.5f * vx * (1.0f + erff(vx * inv_sqrt2));
                    vy = 0.5f * vy * (1.0f + erff(vy * inv_sqrt2));
                } else {
                    const float* rr = E2 + (size_t)r * ldc + c;
                    vx += e1[c]     + rr[0];
                    vy += e1[c + 1] + rr[1];
                }
                *(float2*)(C + (size_t)r * ldc + c) = make_float2(vx, vy);
            }
        }
    }
}

// ============================================================
// Launch
// ============================================================
extern "C" void kernel_launch(void* const* d_in, const int* in_sizes, int n_in,
                              void* d_out, int out_size)
{
    (void)in_sizes; (void)n_in; (void)out_size;
    const float* savespace = (const float*)d_in[1];
    const float* Wqkv      = (const float*)d_in[2];
    const float* Wo        = (const float*)d_in[3];
    const float* ln1_g     = (const float*)d_in[4];
    const float* ln1_b     = (const float*)d_in[5];
    const float* ln2_g     = (const float*)d_in[6];
    const float* ln2_b     = (const float*)d_in[7];
    const float* fc1_w     = (const float*)d_in[8];
    const float* fc1_b     = (const float*)d_in[9];
    const float* fc2_w     = (const float*)d_in[10];
    const float* fc2_b     = (const float*)d_in[11];
    float* out = (float*)d_out;

    float *p_sln, *p_s2, *p_hln, *p_h1, *p_G, *p_Gp, *p_T, *p_ET, *p_ws;
    cudaGetSymbolAddress((void**)&p_sln, g_sln);
    cudaGetSymbolAddress((void**)&p_s2,  g_s2);
    cudaGetSymbolAddress((void**)&p_hln, g_hln);
    cudaGetSymbolAddress((void**)&p_h1,  g_h1);
    cudaGetSymbolAddress((void**)&p_G,   g_G);
    cudaGetSymbolAddress((void**)&p_Gp,  g_Gp);
    cudaGetSymbolAddress((void**)&p_T,   g_T);
    cudaGetSymbolAddress((void**)&p_ET,  g_ET);
    cudaGetSymbolAddress((void**)&p_ws,  g_wosum);

    const long SLAB = (long)J_ * M_;
    const long MM   = MM_;

    // 1) layernorm1
    ln_kernel<<<RTOT, 256>>>(savespace, ln1_g, ln1_b, p_sln);
    // 2) Gram partials + reduce
    gram_kernel<<<dim3(4, 4, NSLAB * NCH), 256>>>(p_sln, p_Gp);
    gram_reduce<<<dim3(64, NSLAB), 256>>>(p_Gp, p_G);
    // 3) Wo row sums
    rowsum_kernel<<<32, 256>>>(Wo, p_ws);
    // 4) T = G @ Wv_full^T per slab
    gemm64<<<dim3(4, 4, NSLAB), 256>>>(
        p_G, M_, MM,  Wqkv + 2 * H_ * DH_ * M_, M_, 0,  p_T, M_, MM, M_);
    // 5) finish ET per (head, slab)
    assemble2_kernel<<<dim3(H_, NSLAB), 256>>>(Wqkv, p_T, p_ET);
    // 6) s2 = wosum * (s_ln @ E) + savespace   [split-bf16, batched]
    bf16_gemm<<<dim3(9, 2, NSLAB), 256>>>(
        p_sln, M_, SLAB,  p_ET, M_, MM,  p_s2, M_, SLAB,
        M_, J_, 0, p_ws, savespace, SLAB);
    // 7) layernorm2
    ln_kernel<<<RTOT, 256>>>(p_s2, ln2_g, ln2_b, p_hln);
    // 8) h1 = gelu(hln @ fc1_w^T + b1)   [split-bf16]
    bf16_gemm<<<dim3(129, 8, 1), 256>>>(
        p_hln, M_, 0,  fc1_w, M_, 0,  p_h1, FF_, 0,
        M_, RTOT, 1, fc1_b, (const float*)0, 0);
    // 9) out = h1 @ fc2_w^T + b2 + s2    [split-bf16]
    bf16_gemm<<<dim3(129, 2, 1), 256>>>(
        p_h1, FF_, 0,  fc2_w, FF_, 0,  out, M_, 0,
        FF_, RTOT, 2, fc2_b, p_s2, 0);
}